// round 1
// baseline (speedup 1.0000x reference)
#include <cuda_runtime.h>
#include <math.h>

// Problem constants
#define BB 4
#define SS 1024
#define DD 1024
#define HH 16
#define HD 64

// Scratch (allocation-free: __device__ globals)
__device__ float g_Q[BB*HH*SS*HD];           // [b,h,s,hd]
__device__ float g_K[BB*HH*SS*HD];
__device__ float g_V[BB*HH*SS*HD];
__device__ float g_X[BB*SS*DD];              // [b,s,d] attention output
__device__ float g_P[(size_t)BB*HH*SS*SS];   // [b,h,q,k] scores then probs (256MB)

// ---------------------------------------------------------------------------
// Generic 4096x1024x1024 SGEMM with bias.
// mode 0: A = g_X, C = Cext, plain [row,col] layout (out projection)
// mode 1/2/3: A = Aext, C = g_Q/g_K/g_V, head layout [b,h,s,hd]
// ---------------------------------------------------------------------------
__global__ __launch_bounds__(256) void gemm128(
    const float* __restrict__ Aext, const float* __restrict__ W,
    const float* __restrict__ bias, float* __restrict__ Cext, int mode)
{
    const int M = 4096, N = 1024, K = 1024;
    (void)M;
    __shared__ float As[8][128];
    __shared__ float Bs[8][128];

    const float* A = (mode == 0) ? g_X : Aext;

    const int tid  = threadIdx.x;
    const int brow = blockIdx.y * 128;
    const int bcol = blockIdx.x * 128;
    const int arow = tid >> 1;            // 0..127
    const int acol = (tid & 1) << 2;      // 0 or 4
    const int brl  = tid >> 5;            // 0..7
    const int bcl  = (tid & 31) << 2;     // 0..124
    const int ty   = tid >> 4;            // 0..15
    const int tx   = tid & 15;            // 0..15

    float acc[8][8];
    #pragma unroll
    for (int i = 0; i < 8; i++)
        #pragma unroll
        for (int j = 0; j < 8; j++) acc[i][j] = 0.f;

    for (int k0 = 0; k0 < K; k0 += 8) {
        float4 av = *reinterpret_cast<const float4*>(
            A + (size_t)(brow + arow) * K + k0 + acol);
        As[acol+0][arow] = av.x; As[acol+1][arow] = av.y;
        As[acol+2][arow] = av.z; As[acol+3][arow] = av.w;
        *reinterpret_cast<float4*>(&Bs[brl][bcl]) =
            *reinterpret_cast<const float4*>(W + (size_t)(k0 + brl) * N + bcol + bcl);
        __syncthreads();
        #pragma unroll
        for (int k = 0; k < 8; k++) {
            float4 a0 = *reinterpret_cast<float4*>(&As[k][ty*8]);
            float4 a1 = *reinterpret_cast<float4*>(&As[k][ty*8+4]);
            float4 b0 = *reinterpret_cast<float4*>(&Bs[k][tx*8]);
            float4 b1 = *reinterpret_cast<float4*>(&Bs[k][tx*8+4]);
            float ar[8] = {a0.x,a0.y,a0.z,a0.w,a1.x,a1.y,a1.z,a1.w};
            float br[8] = {b0.x,b0.y,b0.z,b0.w,b1.x,b1.y,b1.z,b1.w};
            #pragma unroll
            for (int i = 0; i < 8; i++)
                #pragma unroll
                for (int j = 0; j < 8; j++)
                    acc[i][j] = fmaf(ar[i], br[j], acc[i][j]);
        }
        __syncthreads();
    }

    float* Chead = (mode == 1) ? g_Q : (mode == 2) ? g_K : g_V;

    #pragma unroll
    for (int i = 0; i < 8; i++) {
        int row = brow + ty*8 + i;
        #pragma unroll
        for (int j = 0; j < 8; j++) {
            int col = bcol + tx*8 + j;
            float v = acc[i][j] + bias[col];
            if (mode == 0) {
                Cext[(size_t)row * N + col] = v;
            } else {
                int b = row >> 10, s = row & 1023;
                int h = col >> 6,  hd = col & 63;
                Chead[((size_t)((b << 4) + h) * 1024 + s) * 64 + hd] = v;
            }
        }
    }
}

// ---------------------------------------------------------------------------
// Scores: per (b,h): P[1024,1024] = Q[1024,64] @ K[1024,64]^T * 0.125
// 64x64 tiles, 256 threads, 4x4 micro-tile, full K=64 staged in smem.
// ---------------------------------------------------------------------------
__global__ __launch_bounds__(256) void scores_kernel()
{
    const int bh = blockIdx.z;
    const int m0 = blockIdx.y * 64;
    const int n0 = blockIdx.x * 64;
    const float* Q  = g_Q + (size_t)bh * SS * HD;
    const float* Km = g_K + (size_t)bh * SS * HD;
    float* Pp = g_P + (size_t)bh * SS * SS;

    __shared__ float Qs[64][64];   // [k][row]
    __shared__ float Ks[64][64];   // [k][col]

    const int tid = threadIdx.x;
    const int lr  = tid >> 4;           // 0..15
    const int lc  = (tid & 15) << 2;    // 0..60
    #pragma unroll
    for (int r = 0; r < 4; r++) {
        int row = lr + r * 16;
        float4 q4 = *reinterpret_cast<const float4*>(Q + (size_t)(m0 + row) * 64 + lc);
        Qs[lc+0][row] = q4.x; Qs[lc+1][row] = q4.y;
        Qs[lc+2][row] = q4.z; Qs[lc+3][row] = q4.w;
        float4 k4 = *reinterpret_cast<const float4*>(Km + (size_t)(n0 + row) * 64 + lc);
        Ks[lc+0][row] = k4.x; Ks[lc+1][row] = k4.y;
        Ks[lc+2][row] = k4.z; Ks[lc+3][row] = k4.w;
    }
    __syncthreads();

    const int ty = tid >> 4, tx = tid & 15;
    float acc[4][4];
    #pragma unroll
    for (int i = 0; i < 4; i++)
        #pragma unroll
        for (int j = 0; j < 4; j++) acc[i][j] = 0.f;

    #pragma unroll 8
    for (int k = 0; k < 64; k++) {
        float4 a = *reinterpret_cast<float4*>(&Qs[k][ty*4]);
        float4 b = *reinterpret_cast<float4*>(&Ks[k][tx*4]);
        float ar[4] = {a.x,a.y,a.z,a.w};
        float br[4] = {b.x,b.y,b.z,b.w};
        #pragma unroll
        for (int i = 0; i < 4; i++)
            #pragma unroll
            for (int j = 0; j < 4; j++)
                acc[i][j] = fmaf(ar[i], br[j], acc[i][j]);
    }

    #pragma unroll
    for (int i = 0; i < 4; i++) {
        int row = m0 + ty*4 + i;
        float4 o = make_float4(acc[i][0]*0.125f, acc[i][1]*0.125f,
                               acc[i][2]*0.125f, acc[i][3]*0.125f);
        *reinterpret_cast<float4*>(Pp + (size_t)row * SS + n0 + tx*4) = o;
    }
}

// ---------------------------------------------------------------------------
// Softmax over each P row + fused attn_c = sum_h Wc[h]*p + bc.
// One block per (b,q); loops over h=0..15. 256 threads, 4 cols each.
// ---------------------------------------------------------------------------
__global__ __launch_bounds__(256) void softmax_attnc(
    const float* __restrict__ Wc, const float* __restrict__ bcp,
    float* __restrict__ attn_out)
{
    const int b = blockIdx.x >> 10;
    const int q = blockIdx.x & 1023;
    const int tid = threadIdx.x;
    const int lane = tid & 31, wrp = tid >> 5;

    __shared__ float red[8];
    __shared__ float bcast;

    float acc0 = 0.f, acc1 = 0.f, acc2 = 0.f, acc3 = 0.f;

    for (int h = 0; h < HH; h++) {
        float* row = g_P + ((size_t)((b << 4) + h) * SS + q) * SS;
        float4 v = *reinterpret_cast<float4*>(row + (tid << 2));

        // block max
        float m = fmaxf(fmaxf(v.x, v.y), fmaxf(v.z, v.w));
        #pragma unroll
        for (int o = 16; o; o >>= 1) m = fmaxf(m, __shfl_xor_sync(0xffffffffu, m, o));
        if (lane == 0) red[wrp] = m;
        __syncthreads();
        if (tid == 0) {
            float r = red[0];
            #pragma unroll
            for (int i = 1; i < 8; i++) r = fmaxf(r, red[i]);
            bcast = r;
        }
        __syncthreads();
        m = bcast;

        float e0 = expf(v.x - m), e1 = expf(v.y - m);
        float e2 = expf(v.z - m), e3 = expf(v.w - m);

        // block sum
        float s = e0 + e1 + e2 + e3;
        #pragma unroll
        for (int o = 16; o; o >>= 1) s += __shfl_xor_sync(0xffffffffu, s, o);
        __syncthreads();           // bcast(max) reads done before red reuse-by-sumpath ordering
        if (lane == 0) red[wrp] = s;
        __syncthreads();
        if (tid == 0) {
            float r = 0.f;
            #pragma unroll
            for (int i = 0; i < 8; i++) r += red[i];
            bcast = r;
        }
        __syncthreads();
        float inv = 1.f / bcast;
        __syncthreads();           // all have read bcast before next-iter overwrite

        float p0 = e0 * inv, p1 = e1 * inv, p2 = e2 * inv, p3 = e3 * inv;
        *reinterpret_cast<float4*>(row + (tid << 2)) = make_float4(p0, p1, p2, p3);

        float w = Wc[h];
        acc0 = fmaf(w, p0, acc0); acc1 = fmaf(w, p1, acc1);
        acc2 = fmaf(w, p2, acc2); acc3 = fmaf(w, p3, acc3);
    }

    float bcv = bcp[0];
    float4 o = make_float4(acc0 + bcv, acc1 + bcv, acc2 + bcv, acc3 + bcv);
    *reinterpret_cast<float4*>(attn_out + ((size_t)b * SS + q) * SS + (tid << 2)) = o;
}

// ---------------------------------------------------------------------------
// PV: per (b,h): X[1024,64] = P[1024,1024] @ V[1024,64], written into g_X[b,s,d].
// 64-row M-tiles, full N=64, BK=16, 256 threads, 4x4 micro-tile.
// ---------------------------------------------------------------------------
__global__ __launch_bounds__(256) void pv_kernel()
{
    const int bh = blockIdx.y;
    const int m0 = blockIdx.x * 64;
    const float* Pp = g_P + (size_t)bh * SS * SS + (size_t)m0 * SS;
    const float* V  = g_V + (size_t)bh * SS * HD;
    const int b = bh >> 4, h = bh & 15;

    __shared__ float Ps[16][64];   // [k][m]
    __shared__ float Vs[16][64];   // [k][n]

    const int tid = threadIdx.x;
    const int pr = tid >> 2;            // 0..63
    const int pc = (tid & 3) << 2;      // 0..12
    const int vr = tid >> 4;            // 0..15
    const int vc = (tid & 15) << 2;     // 0..60
    const int ty = tid >> 4, tx = tid & 15;

    float acc[4][4];
    #pragma unroll
    for (int i = 0; i < 4; i++)
        #pragma unroll
        for (int j = 0; j < 4; j++) acc[i][j] = 0.f;

    for (int k0 = 0; k0 < SS; k0 += 16) {
        float4 p4 = *reinterpret_cast<const float4*>(Pp + (size_t)pr * SS + k0 + pc);
        Ps[pc+0][pr] = p4.x; Ps[pc+1][pr] = p4.y;
        Ps[pc+2][pr] = p4.z; Ps[pc+3][pr] = p4.w;
        *reinterpret_cast<float4*>(&Vs[vr][vc]) =
            *reinterpret_cast<const float4*>(V + (size_t)(k0 + vr) * 64 + vc);
        __syncthreads();
        #pragma unroll
        for (int k = 0; k < 16; k++) {
            float4 a = *reinterpret_cast<float4*>(&Ps[k][ty*4]);
            float4 bv = *reinterpret_cast<float4*>(&Vs[k][tx*4]);
            float ar[4] = {a.x,a.y,a.z,a.w};
            float br[4] = {bv.x,bv.y,bv.z,bv.w};
            #pragma unroll
            for (int i = 0; i < 4; i++)
                #pragma unroll
                for (int j = 0; j < 4; j++)
                    acc[i][j] = fmaf(ar[i], br[j], acc[i][j]);
        }
        __syncthreads();
    }

    #pragma unroll
    for (int i = 0; i < 4; i++) {
        int s = m0 + ty*4 + i;
        float4 o = make_float4(acc[i][0], acc[i][1], acc[i][2], acc[i][3]);
        *reinterpret_cast<float4*>(
            g_X + ((size_t)b * SS + s) * DD + h * 64 + tx*4) = o;
    }
}

// ---------------------------------------------------------------------------
extern "C" void kernel_launch(void* const* d_in, const int* in_sizes, int n_in,
                              void* d_out, int out_size)
{
    (void)in_sizes; (void)n_in; (void)out_size;
    const float* query = (const float*)d_in[0];
    const float* key   = (const float*)d_in[1];
    const float* value = (const float*)d_in[2];
    const float* Wq = (const float*)d_in[3];  const float* bq = (const float*)d_in[4];
    const float* Wk = (const float*)d_in[5];  const float* bk = (const float*)d_in[6];
    const float* Wv = (const float*)d_in[7];  const float* bv = (const float*)d_in[8];
    const float* Wo = (const float*)d_in[9];  const float* bo = (const float*)d_in[10];
    const float* Wc = (const float*)d_in[11]; const float* bc = (const float*)d_in[12];

    float* out = (float*)d_out;
    float* attn_out = out + (size_t)BB * SS * DD;

    dim3 ggrid(DD / 128, (BB * SS) / 128);   // (8, 32)

    // Q/K/V projections -> head layout scratch
    gemm128<<<ggrid, 256>>>(query, Wq, bq, nullptr, 1);
    gemm128<<<ggrid, 256>>>(key,   Wk, bk, nullptr, 2);
    gemm128<<<ggrid, 256>>>(value, Wv, bv, nullptr, 3);

    // scores = Q K^T / 8  -> g_P
    scores_kernel<<<dim3(SS/64, SS/64, BB*HH), 256>>>();

    // softmax in-place on g_P + fused attn_c output
    softmax_attnc<<<BB * SS, 256>>>(Wc, bc, attn_out);

    // X = P @ V -> g_X [b,s,d]
    pv_kernel<<<dim3(SS/64, BB*HH), 256>>>();

    // out = X @ Wo + bo -> d_out
    gemm128<<<ggrid, 256>>>(nullptr, Wo, bo, out, 0);
}

// round 4
// speedup vs baseline: 2.9535x; 2.9535x over previous
#include <cuda_runtime.h>
#include <cuda_bf16.h>
#include <math.h>
#include <stdint.h>

#define BB 4
#define SS 1024
#define DD 1024
#define HH 16
#define HD 64

typedef unsigned short ushort_t;

// ---------------------------------------------------------------------------
// Scratch (__device__ globals; allocation-free)
// ---------------------------------------------------------------------------
__device__ float    g_P  [(size_t)BB*HH*SS*SS];   // fp32 scores (256MB)
__device__ ushort_t g_Phi[(size_t)BB*HH*SS*SS];   // probs hi (128MB)
__device__ ushort_t g_Plo[(size_t)BB*HH*SS*SS];   // probs lo (128MB)
__device__ ushort_t g_Qhi[BB*HH*SS*HD], g_Qlo[BB*HH*SS*HD];
__device__ ushort_t g_Khi[BB*HH*SS*HD], g_Klo[BB*HH*SS*HD];
__device__ ushort_t g_Vhi[BB*HH*SS*HD], g_Vlo[BB*HH*SS*HD];
__device__ ushort_t g_Xhi[BB*SS*DD],    g_Xlo[BB*SS*DD];
__device__ ushort_t g_Ahi[BB*SS*DD],    g_Alo[BB*SS*DD];   // activation split
__device__ ushort_t g_Bhi[DD*DD],       g_Blo[DD*DD];      // W^T split

// ---------------------------------------------------------------------------
// Base-ISA helpers (compute_103-safe: mma.sync / ldmatrix / cp.async)
// ---------------------------------------------------------------------------
__device__ __forceinline__ uint32_t smem_to_u32(const void* p) {
    uint32_t a;
    asm("{ .reg .u64 t; cvta.to.shared.u64 t, %1; cvt.u32.u64 %0, t; }"
        : "=r"(a) : "l"(p));
    return a;
}
__device__ __forceinline__ void cpa16(uint32_t s, const void* g) {
    asm volatile("cp.async.cg.shared.global [%0], [%1], 16;" :: "r"(s), "l"(g));
}
#define CP_COMMIT() asm volatile("cp.async.commit_group;")
#define CP_WAIT(n)  asm volatile("cp.async.wait_group %0;" :: "n"(n))

__device__ __forceinline__ void ldsm4(uint32_t* r, uint32_t addr) {
    asm volatile("ldmatrix.sync.aligned.m8n8.x4.shared.b16 {%0,%1,%2,%3}, [%4];"
        : "=r"(r[0]), "=r"(r[1]), "=r"(r[2]), "=r"(r[3]) : "r"(addr));
}
__device__ __forceinline__ void ldsm4t(uint32_t* r, uint32_t addr) {
    asm volatile("ldmatrix.sync.aligned.m8n8.x4.trans.shared.b16 {%0,%1,%2,%3}, [%4];"
        : "=r"(r[0]), "=r"(r[1]), "=r"(r[2]), "=r"(r[3]) : "r"(addr));
}
__device__ __forceinline__ void mma16816(float* c, const uint32_t* a,
                                         uint32_t b0, uint32_t b1) {
    asm volatile(
        "mma.sync.aligned.m16n8k16.row.col.f32.bf16.bf16.f32 "
        "{%0,%1,%2,%3}, {%4,%5,%6,%7}, {%8,%9}, {%0,%1,%2,%3};"
        : "+f"(c[0]), "+f"(c[1]), "+f"(c[2]), "+f"(c[3])
        : "r"(a[0]), "r"(a[1]), "r"(a[2]), "r"(a[3]), "r"(b0), "r"(b1));
}

__device__ __forceinline__ void split1(float v, ushort_t& h, ushort_t& l) {
    __nv_bfloat16 hb = __float2bfloat16(v);
    float r = v - __bfloat162float(hb);
    __nv_bfloat16 lb = __float2bfloat16(r);
    h = __bfloat16_as_ushort(hb);
    l = __bfloat16_as_ushort(lb);
}

// ---------------------------------------------------------------------------
// split fp32 activations -> bf16 hi/lo (row-major passthrough)
// ---------------------------------------------------------------------------
__global__ __launch_bounds__(256) void split_act(
    const float4* __restrict__ x, uint2* __restrict__ hi, uint2* __restrict__ lo, int n4)
{
    int i = blockIdx.x * blockDim.x + threadIdx.x;
    if (i >= n4) return;
    float4 v = x[i];
    ushort_t h0,h1,h2,h3,l0,l1,l2,l3;
    split1(v.x,h0,l0); split1(v.y,h1,l1); split1(v.z,h2,l2); split1(v.w,h3,l3);
    hi[i] = make_uint2((uint32_t)h0 | ((uint32_t)h1 << 16),
                       (uint32_t)h2 | ((uint32_t)h3 << 16));
    lo[i] = make_uint2((uint32_t)l0 | ((uint32_t)l1 << 16),
                       (uint32_t)l2 | ((uint32_t)l3 << 16));
}

// split + transpose W[K][N] -> W^T[N][K] hi/lo
__global__ __launch_bounds__(256) void split_wT(
    const float* __restrict__ W, ushort_t* __restrict__ hi, ushort_t* __restrict__ lo)
{
    __shared__ float t[32][33];
    int n0 = blockIdx.x * 32, k0 = blockIdx.y * 32;
    int tx = threadIdx.x & 31, ty = threadIdx.x >> 5;
    #pragma unroll
    for (int j = 0; j < 4; j++)
        t[ty + 8*j][tx] = W[(size_t)(k0 + ty + 8*j) * DD + n0 + tx];
    __syncthreads();
    #pragma unroll
    for (int j = 0; j < 4; j++) {
        float v = t[tx][ty + 8*j];
        ushort_t h, l; split1(v, h, l);
        size_t o = (size_t)(n0 + ty + 8*j) * DD + k0 + tx;
        hi[o] = h; lo[o] = l;
    }
}

// ---------------------------------------------------------------------------
// Projection GEMM (HMMA split-3): C[4096,1024] = A * W^T + bias
// A hi/lo row-major [M][K]; B hi/lo row-major [N][K].
// mode 0: fp32 -> Cext.  mode 1: bf16 hi/lo head layout -> Chi/Clo.
// CTA 128x128, BK=32, 8 warps (4M x 2N), warp 32x64.
// ---------------------------------------------------------------------------
#define PJ_TILE  10240            // 128 rows * 40 elems * 2B
#define PJ_STAGE (4*PJ_TILE)      // Ahi|Alo|Bhi|Blo
#define PJ_SMEM  (2*PJ_STAGE)     // 81920

__global__ __launch_bounds__(256) void proj_mma(
    const ushort_t* __restrict__ Ahi, const ushort_t* __restrict__ Alo,
    const ushort_t* __restrict__ Bhi, const ushort_t* __restrict__ Blo,
    const float* __restrict__ bias,
    ushort_t* __restrict__ Chi, ushort_t* __restrict__ Clo,
    float* __restrict__ Cext, int mode)
{
    extern __shared__ char smem[];
    const uint32_t sb = smem_to_u32(smem);
    const int tid = threadIdx.x, lane = tid & 31, wid = tid >> 5;
    const int wm = wid >> 1, wn = wid & 1;
    const int m0 = blockIdx.y * 128, n0 = blockIdx.x * 128;

    const ushort_t* gsrc[4] = {Ahi, Alo, Bhi, Blo};

    auto issue = [&](int stage, int k0) {
        #pragma unroll
        for (int i = 0; i < 8; i++) {
            int cid = i * 256 + tid;
            int t = cid >> 9;                 // tile 0..3
            int idx = cid & 511;
            int r = idx >> 2, c = idx & 3;
            int grow = (t < 2 ? m0 : n0) + r;
            const ushort_t* g = gsrc[t] + (size_t)grow * 1024 + k0 + c * 8;
            cpa16(sb + stage * PJ_STAGE + t * PJ_TILE + r * 80 + c * 16, g);
        }
        CP_COMMIT();
    };

    float acc[2][8][4];
    #pragma unroll
    for (int i = 0; i < 2; i++)
        #pragma unroll
        for (int j = 0; j < 8; j++)
            #pragma unroll
            for (int c = 0; c < 4; c++) acc[i][j][c] = 0.f;

    issue(0, 0);
    for (int kc = 0; kc < 32; kc++) {
        if (kc < 31) { issue((kc + 1) & 1, (kc + 1) * 32); CP_WAIT(1); }
        else CP_WAIT(0);
        __syncthreads();
        const uint32_t s0  = sb + (kc & 1) * PJ_STAGE;
        const uint32_t sAh = s0, sAl = s0 + PJ_TILE;
        const uint32_t sBh = s0 + 2*PJ_TILE, sBl = s0 + 3*PJ_TILE;

        #pragma unroll
        for (int ks = 0; ks < 2; ks++) {
            uint32_t ah[2][4], al[2][4];
            #pragma unroll
            for (int i = 0; i < 2; i++) {
                uint32_t off = (uint32_t)(wm*32 + i*16 + (lane & 15)) * 80
                             + ((lane >> 4) * 16) + ks * 32;
                ldsm4(ah[i], sAh + off);
                ldsm4(al[i], sAl + off);
            }
            uint32_t bh[4][4], bl[4][4];
            #pragma unroll
            for (int j4 = 0; j4 < 4; j4++) {
                uint32_t row = (uint32_t)(wn*64 + j4*16 + (lane & 7) + ((lane & 16) >> 1));
                uint32_t off = row * 80 + ks * 32 + ((lane & 8) << 1);
                ldsm4(bh[j4], sBh + off);
                ldsm4(bl[j4], sBl + off);
            }
            #pragma unroll
            for (int i = 0; i < 2; i++)
                #pragma unroll
                for (int j = 0; j < 8; j++) {
                    int j4 = j >> 1, hh = (j & 1) * 2;
                    mma16816(acc[i][j], ah[i], bh[j4][hh], bh[j4][hh+1]);
                    mma16816(acc[i][j], ah[i], bl[j4][hh], bl[j4][hh+1]);
                    mma16816(acc[i][j], al[i], bh[j4][hh], bh[j4][hh+1]);
                }
        }
        __syncthreads();
    }

    // epilogue
    #pragma unroll
    for (int i = 0; i < 2; i++) {
        int mlo = m0 + wm*32 + i*16 + (lane >> 2);
        #pragma unroll
        for (int half = 0; half < 2; half++) {
            int m = mlo + half * 8;
            int b = m >> 10, s = m & 1023;
            #pragma unroll
            for (int j = 0; j < 8; j++) {
                int col = n0 + wn*64 + j*8 + 2*(lane & 3);
                float v0 = acc[i][j][half*2 + 0] + bias[col];
                float v1 = acc[i][j][half*2 + 1] + bias[col + 1];
                if (mode == 0) {
                    *reinterpret_cast<float2*>(Cext + (size_t)m * 1024 + col)
                        = make_float2(v0, v1);
                } else {
                    int h = col >> 6, hd = col & 63;
                    size_t o = ((size_t)((b << 4) + h) * 1024 + s) * 64 + hd;
                    ushort_t h0,l0,h1,l1;
                    split1(v0, h0, l0); split1(v1, h1, l1);
                    *reinterpret_cast<ushort2*>(Chi + o) = make_ushort2(h0, h1);
                    *reinterpret_cast<ushort2*>(Clo + o) = make_ushort2(l0, l1);
                }
            }
        }
    }
}

// ---------------------------------------------------------------------------
// Scores (HMMA split-3): per (b,h) S[128,128] tile = Q @ K^T * 0.125 -> g_P
// K=64 in one load. smem stride 72 elems (144B rows).
// ---------------------------------------------------------------------------
#define SC_TILE  18432            // 128*72*2
#define SC_SMEM  (4*SC_TILE)      // 73728

__global__ __launch_bounds__(256) void scores_mma()
{
    extern __shared__ char smem[];
    const uint32_t sb = smem_to_u32(smem);
    const int tid = threadIdx.x, lane = tid & 31, wid = tid >> 5;
    const int wm = wid >> 1, wn = wid & 1;
    const int bh = blockIdx.z;
    const int m0 = blockIdx.y * 128, n0 = blockIdx.x * 128;

    const ushort_t* gsrc[4] = {g_Qhi, g_Qlo, g_Khi, g_Klo};

    #pragma unroll
    for (int i = 0; i < 16; i++) {
        int cid = i * 256 + tid;
        int t = cid >> 10;
        int idx = cid & 1023;
        int r = idx >> 3, c = idx & 7;
        int base = (t < 2 ? m0 : n0);
        const ushort_t* g = gsrc[t] + ((size_t)bh * 1024 + base + r) * 64 + c * 8;
        cpa16(sb + t * SC_TILE + r * 144 + c * 16, g);
    }
    CP_COMMIT();
    CP_WAIT(0);
    __syncthreads();

    const uint32_t sQh = sb, sQl = sb + SC_TILE;
    const uint32_t sKh = sb + 2*SC_TILE, sKl = sb + 3*SC_TILE;

    float acc[2][8][4];
    #pragma unroll
    for (int i = 0; i < 2; i++)
        #pragma unroll
        for (int j = 0; j < 8; j++)
            #pragma unroll
            for (int c = 0; c < 4; c++) acc[i][j][c] = 0.f;

    #pragma unroll
    for (int ks = 0; ks < 4; ks++) {
        uint32_t ah[2][4], al[2][4];
        #pragma unroll
        for (int i = 0; i < 2; i++) {
            uint32_t off = (uint32_t)(wm*32 + i*16 + (lane & 15)) * 144
                         + ((lane >> 4) * 16) + ks * 32;
            ldsm4(ah[i], sQh + off);
            ldsm4(al[i], sQl + off);
        }
        uint32_t bh4[4][4], bl4[4][4];
        #pragma unroll
        for (int j4 = 0; j4 < 4; j4++) {
            uint32_t row = (uint32_t)(wn*64 + j4*16 + (lane & 7) + ((lane & 16) >> 1));
            uint32_t off = row * 144 + ks * 32 + ((lane & 8) << 1);
            ldsm4(bh4[j4], sKh + off);
            ldsm4(bl4[j4], sKl + off);
        }
        #pragma unroll
        for (int i = 0; i < 2; i++)
            #pragma unroll
            for (int j = 0; j < 8; j++) {
                int j4 = j >> 1, hh = (j & 1) * 2;
                mma16816(acc[i][j], ah[i], bh4[j4][hh], bh4[j4][hh+1]);
                mma16816(acc[i][j], ah[i], bl4[j4][hh], bl4[j4][hh+1]);
                mma16816(acc[i][j], al[i], bh4[j4][hh], bh4[j4][hh+1]);
            }
    }

    float* Pp = g_P + (size_t)bh * SS * SS;
    #pragma unroll
    for (int i = 0; i < 2; i++) {
        int mlo = m0 + wm*32 + i*16 + (lane >> 2);
        #pragma unroll
        for (int half = 0; half < 2; half++) {
            int m = mlo + half * 8;
            #pragma unroll
            for (int j = 0; j < 8; j++) {
                int col = n0 + wn*64 + j*8 + 2*(lane & 3);
                *reinterpret_cast<float2*>(Pp + (size_t)m * SS + col)
                    = make_float2(acc[i][j][half*2+0] * 0.125f,
                                  acc[i][j][half*2+1] * 0.125f);
            }
        }
    }
}

// ---------------------------------------------------------------------------
// Softmax per (b,q) row across all heads; emits P hi/lo bf16 + attn_c.
// ---------------------------------------------------------------------------
__global__ __launch_bounds__(256) void softmax_attnc(
    const float* __restrict__ Wc, const float* __restrict__ bcp,
    float* __restrict__ attn_out)
{
    const int b = blockIdx.x >> 10;
    const int q = blockIdx.x & 1023;
    const int tid = threadIdx.x;
    const int lane = tid & 31, wrp = tid >> 5;

    __shared__ float red[8];
    __shared__ float bcast;

    float acc0 = 0.f, acc1 = 0.f, acc2 = 0.f, acc3 = 0.f;

    for (int h = 0; h < HH; h++) {
        size_t rowoff = ((size_t)((b << 4) + h) * SS + q) * SS;
        const float* row = g_P + rowoff;
        float4 v = *reinterpret_cast<const float4*>(row + (tid << 2));

        float m = fmaxf(fmaxf(v.x, v.y), fmaxf(v.z, v.w));
        #pragma unroll
        for (int o = 16; o; o >>= 1) m = fmaxf(m, __shfl_xor_sync(0xffffffffu, m, o));
        if (lane == 0) red[wrp] = m;
        __syncthreads();
        if (tid == 0) {
            float r = red[0];
            #pragma unroll
            for (int i = 1; i < 8; i++) r = fmaxf(r, red[i]);
            bcast = r;
        }
        __syncthreads();
        m = bcast;

        float e0 = expf(v.x - m), e1 = expf(v.y - m);
        float e2 = expf(v.z - m), e3 = expf(v.w - m);

        float s = e0 + e1 + e2 + e3;
        #pragma unroll
        for (int o = 16; o; o >>= 1) s += __shfl_xor_sync(0xffffffffu, s, o);
        __syncthreads();
        if (lane == 0) red[wrp] = s;
        __syncthreads();
        if (tid == 0) {
            float r = 0.f;
            #pragma unroll
            for (int i = 0; i < 8; i++) r += red[i];
            bcast = r;
        }
        __syncthreads();
        float inv = 1.f / bcast;
        __syncthreads();

        float p0 = e0 * inv, p1 = e1 * inv, p2 = e2 * inv, p3 = e3 * inv;

        ushort_t h0,l0,h1,l1,h2,l2,h3,l3;
        split1(p0,h0,l0); split1(p1,h1,l1); split1(p2,h2,l2); split1(p3,h3,l3);
        uint2 hv = make_uint2((uint32_t)h0 | ((uint32_t)h1 << 16),
                              (uint32_t)h2 | ((uint32_t)h3 << 16));
        uint2 lv = make_uint2((uint32_t)l0 | ((uint32_t)l1 << 16),
                              (uint32_t)l2 | ((uint32_t)l3 << 16));
        *reinterpret_cast<uint2*>(g_Phi + rowoff + (tid << 2)) = hv;
        *reinterpret_cast<uint2*>(g_Plo + rowoff + (tid << 2)) = lv;

        float w = Wc[h];
        acc0 = fmaf(w, p0, acc0); acc1 = fmaf(w, p1, acc1);
        acc2 = fmaf(w, p2, acc2); acc3 = fmaf(w, p3, acc3);
    }

    float bcv = bcp[0];
    *reinterpret_cast<float4*>(attn_out + ((size_t)b * SS + q) * SS + (tid << 2))
        = make_float4(acc0 + bcv, acc1 + bcv, acc2 + bcv, acc3 + bcv);
}

// ---------------------------------------------------------------------------
// PV (HMMA split-3): per (b,h) X[128,64] tile = P @ V -> g_Xhi/g_Xlo [b,s,d]
// P A-side row-major; V consumed via ldmatrix.trans (smem [k][n]).
// CTA 128x64, BK=32, 8 warps (4M x 2N), warp 32x32.
// ---------------------------------------------------------------------------
#define PV_PTILE 10240            // 128*40*2
#define PV_VTILE 4608             // 32*72*2
#define PV_STAGE (2*PV_PTILE + 2*PV_VTILE)   // 29696
#define PV_SMEM  (2*PV_STAGE)                // 59392

__global__ __launch_bounds__(256) void pv_mma()
{
    extern __shared__ char smem[];
    const uint32_t sb = smem_to_u32(smem);
    const int tid = threadIdx.x, lane = tid & 31, wid = tid >> 5;
    const int wm = wid >> 1, wn = wid & 1;
    const int bh = blockIdx.y;
    const int m0 = blockIdx.x * 128;
    const int b = bh >> 4, h = bh & 15;

    auto issue = [&](int stage, int k0) {
        uint32_t s0 = sb + stage * PV_STAGE;
        #pragma unroll
        for (int i = 0; i < 6; i++) {
            int cid = i * 256 + tid;
            if (cid < 1024) {                      // P hi/lo: 2 x 512 chunks
                int t = cid >> 9;                  // 0 hi, 1 lo
                int idx = cid & 511;
                int r = idx >> 2, c = idx & 3;
                const ushort_t* g = (t ? g_Plo : g_Phi)
                    + ((size_t)bh * 1024 + m0 + r) * 1024 + k0 + c * 8;
                cpa16(s0 + t * PV_PTILE + r * 80 + c * 16, g);
            } else {                               // V hi/lo: 2 x 256 chunks
                int cc = cid - 1024;
                int t = cc >> 8;
                int idx = cc & 255;
                int r = idx >> 3, c = idx & 7;
                const ushort_t* g = (t ? g_Vlo : g_Vhi)
                    + ((size_t)bh * 1024 + k0 + r) * 64 + c * 8;
                cpa16(s0 + 2 * PV_PTILE + t * PV_VTILE + r * 144 + c * 16, g);
            }
        }
        CP_COMMIT();
    };

    float acc[2][4][4];
    #pragma unroll
    for (int i = 0; i < 2; i++)
        #pragma unroll
        for (int j = 0; j < 4; j++)
            #pragma unroll
            for (int c = 0; c < 4; c++) acc[i][j][c] = 0.f;

    issue(0, 0);
    for (int kc = 0; kc < 32; kc++) {
        if (kc < 31) { issue((kc + 1) & 1, (kc + 1) * 32); CP_WAIT(1); }
        else CP_WAIT(0);
        __syncthreads();
        const uint32_t s0  = sb + (kc & 1) * PV_STAGE;
        const uint32_t sPh = s0, sPl = s0 + PV_PTILE;
        const uint32_t sVh = s0 + 2*PV_PTILE, sVl = sVh + PV_VTILE;

        #pragma unroll
        for (int ks = 0; ks < 2; ks++) {
            uint32_t ah[2][4], al[2][4];
            #pragma unroll
            for (int i = 0; i < 2; i++) {
                uint32_t off = (uint32_t)(wm*32 + i*16 + (lane & 15)) * 80
                             + ((lane >> 4) * 16) + ks * 32;
                ldsm4(ah[i], sPh + off);
                ldsm4(al[i], sPl + off);
            }
            uint32_t bh2[2][4], bl2[2][4];
            #pragma unroll
            for (int j2 = 0; j2 < 2; j2++) {
                uint32_t row = (uint32_t)(ks*16 + (lane & 7) + ((lane & 8) ? 8 : 0));
                uint32_t col = (uint32_t)(wn*32 + j2*16 + ((lane & 16) ? 8 : 0));
                uint32_t off = row * 144 + col * 2;
                ldsm4t(bh2[j2], sVh + off);
                ldsm4t(bl2[j2], sVl + off);
            }
            #pragma unroll
            for (int i = 0; i < 2; i++)
                #pragma unroll
                for (int j = 0; j < 4; j++) {
                    int j2 = j >> 1, hh = (j & 1) * 2;
                    mma16816(acc[i][j], ah[i], bh2[j2][hh], bh2[j2][hh+1]);
                    mma16816(acc[i][j], ah[i], bl2[j2][hh], bl2[j2][hh+1]);
                    mma16816(acc[i][j], al[i], bh2[j2][hh], bh2[j2][hh+1]);
                }
        }
        __syncthreads();
    }

    #pragma unroll
    for (int i = 0; i < 2; i++) {
        int qlo = m0 + wm*32 + i*16 + (lane >> 2);
        #pragma unroll
        for (int half = 0; half < 2; half++) {
            int q = qlo + half * 8;
            #pragma unroll
            for (int j = 0; j < 4; j++) {
                int hd = wn*32 + j*8 + 2*(lane & 3);
                float v0 = acc[i][j][half*2 + 0];
                float v1 = acc[i][j][half*2 + 1];
                size_t o = ((size_t)(b * 1024 + q)) * 1024 + h * 64 + hd;
                ushort_t h0,l0,h1,l1;
                split1(v0, h0, l0); split1(v1, h1, l1);
                *reinterpret_cast<ushort2*>(g_Xhi + o) = make_ushort2(h0, h1);
                *reinterpret_cast<ushort2*>(g_Xlo + o) = make_ushort2(l0, l1);
            }
        }
    }
}

// ---------------------------------------------------------------------------
extern "C" void kernel_launch(void* const* d_in, const int* in_sizes, int n_in,
                              void* d_out, int out_size)
{
    (void)in_sizes; (void)n_in; (void)out_size;
    const float* query = (const float*)d_in[0];
    const float* key   = (const float*)d_in[1];
    const float* value = (const float*)d_in[2];
    const float* Wq = (const float*)d_in[3];  const float* bq = (const float*)d_in[4];
    const float* Wk = (const float*)d_in[5];  const float* bk = (const float*)d_in[6];
    const float* Wv = (const float*)d_in[7];  const float* bv = (const float*)d_in[8];
    const float* Wo = (const float*)d_in[9];  const float* bo = (const float*)d_in[10];
    const float* Wc = (const float*)d_in[11]; const float* bc = (const float*)d_in[12];

    float* out = (float*)d_out;
    float* attn_out = out + (size_t)BB * SS * DD;

    static bool attr_done = false;
    if (!attr_done) {
        cudaFuncSetAttribute(proj_mma,   cudaFuncAttributeMaxDynamicSharedMemorySize, PJ_SMEM);
        cudaFuncSetAttribute(scores_mma, cudaFuncAttributeMaxDynamicSharedMemorySize, SC_SMEM);
        cudaFuncSetAttribute(pv_mma,     cudaFuncAttributeMaxDynamicSharedMemorySize, PV_SMEM);
        attr_done = true;
    }

    ushort_t *Ahi, *Alo, *Bhi, *Blo, *Qhi, *Qlo, *Khi, *Klo, *Vhi, *Vlo, *Xhi, *Xlo;
    cudaGetSymbolAddress((void**)&Ahi, g_Ahi); cudaGetSymbolAddress((void**)&Alo, g_Alo);
    cudaGetSymbolAddress((void**)&Bhi, g_Bhi); cudaGetSymbolAddress((void**)&Blo, g_Blo);
    cudaGetSymbolAddress((void**)&Qhi, g_Qhi); cudaGetSymbolAddress((void**)&Qlo, g_Qlo);
    cudaGetSymbolAddress((void**)&Khi, g_Khi); cudaGetSymbolAddress((void**)&Klo, g_Klo);
    cudaGetSymbolAddress((void**)&Vhi, g_Vhi); cudaGetSymbolAddress((void**)&Vlo, g_Vlo);
    cudaGetSymbolAddress((void**)&Xhi, g_Xhi); cudaGetSymbolAddress((void**)&Xlo, g_Xlo);

    const int NACT4 = BB * SS * DD / 4;
    dim3 pgrid(8, 32);       // N/128, M/128
    dim3 wgrid(32, 32);

    // Q projection
    split_act<<<NACT4/256, 256>>>((const float4*)query, (uint2*)Ahi, (uint2*)Alo, NACT4);
    split_wT<<<wgrid, 256>>>(Wq, Bhi, Blo);
    proj_mma<<<pgrid, 256, PJ_SMEM>>>(Ahi, Alo, Bhi, Blo, bq, Qhi, Qlo, nullptr, 1);
    // K projection
    split_act<<<NACT4/256, 256>>>((const float4*)key, (uint2*)Ahi, (uint2*)Alo, NACT4);
    split_wT<<<wgrid, 256>>>(Wk, Bhi, Blo);
    proj_mma<<<pgrid, 256, PJ_SMEM>>>(Ahi, Alo, Bhi, Blo, bk, Khi, Klo, nullptr, 1);
    // V projection
    split_act<<<NACT4/256, 256>>>((const float4*)value, (uint2*)Ahi, (uint2*)Alo, NACT4);
    split_wT<<<wgrid, 256>>>(Wv, Bhi, Blo);
    proj_mma<<<pgrid, 256, PJ_SMEM>>>(Ahi, Alo, Bhi, Blo, bv, Vhi, Vlo, nullptr, 1);

    // scores -> g_P
    scores_mma<<<dim3(8, 8, BB*HH), 256, SC_SMEM>>>();

    // softmax -> Phi/Plo + attn_c
    softmax_attnc<<<BB * SS, 256>>>(Wc, bc, attn_out);

    // PV -> Xhi/Xlo
    pv_mma<<<dim3(8, BB*HH), 256, PV_SMEM>>>();

    // out projection (A = Xhi/Xlo directly)
    split_wT<<<wgrid, 256>>>(Wo, Bhi, Blo);
    proj_mma<<<pgrid, 256, PJ_SMEM>>>(Xhi, Xlo, Bhi, Blo, bo, nullptr, nullptr, out, 0);
}

// round 5
// speedup vs baseline: 2.9591x; 1.0019x over previous
#include <cuda_runtime.h>
#include <cuda_bf16.h>
#include <math.h>
#include <stdint.h>

#define BB 4
#define SS 1024
#define DD 1024
#define HH 16
#define HD 64

typedef unsigned short ushort_t;

// ---------------------------------------------------------------------------
// Scratch (__device__ globals; allocation-free)
// ---------------------------------------------------------------------------
__device__ float    g_P  [(size_t)BB*HH*SS*SS];   // fp32 scores (256MB)
__device__ ushort_t g_Phi[(size_t)BB*HH*SS*SS];   // probs hi (128MB)
__device__ ushort_t g_Plo[(size_t)BB*HH*SS*SS];   // probs lo (128MB)
__device__ ushort_t g_Qhi[BB*HH*SS*HD], g_Qlo[BB*HH*SS*HD];
__device__ ushort_t g_Khi[BB*HH*SS*HD], g_Klo[BB*HH*SS*HD];
__device__ ushort_t g_Vhi[BB*HH*SS*HD], g_Vlo[BB*HH*SS*HD];
__device__ ushort_t g_Xhi[BB*SS*DD],    g_Xlo[BB*SS*DD];
__device__ ushort_t g_Ahi[BB*SS*DD],    g_Alo[BB*SS*DD];   // activation split
__device__ ushort_t g_Bhi[DD*DD],       g_Blo[DD*DD];      // W^T split

// ---------------------------------------------------------------------------
// Base-ISA helpers (compute_103-safe: mma.sync / ldmatrix / cp.async)
// ---------------------------------------------------------------------------
__device__ __forceinline__ uint32_t smem_to_u32(const void* p) {
    uint32_t a;
    asm("{ .reg .u64 t; cvta.to.shared.u64 t, %1; cvt.u32.u64 %0, t; }"
        : "=r"(a) : "l"(p));
    return a;
}
__device__ __forceinline__ void cpa16(uint32_t s, const void* g) {
    asm volatile("cp.async.cg.shared.global [%0], [%1], 16;" :: "r"(s), "l"(g));
}
#define CP_COMMIT() asm volatile("cp.async.commit_group;")
#define CP_WAIT(n)  asm volatile("cp.async.wait_group %0;" :: "n"(n))

__device__ __forceinline__ void ldsm4(uint32_t* r, uint32_t addr) {
    asm volatile("ldmatrix.sync.aligned.m8n8.x4.shared.b16 {%0,%1,%2,%3}, [%4];"
        : "=r"(r[0]), "=r"(r[1]), "=r"(r[2]), "=r"(r[3]) : "r"(addr));
}
__device__ __forceinline__ void ldsm4t(uint32_t* r, uint32_t addr) {
    asm volatile("ldmatrix.sync.aligned.m8n8.x4.trans.shared.b16 {%0,%1,%2,%3}, [%4];"
        : "=r"(r[0]), "=r"(r[1]), "=r"(r[2]), "=r"(r[3]) : "r"(addr));
}
__device__ __forceinline__ void mma16816(float* c, const uint32_t* a,
                                         uint32_t b0, uint32_t b1) {
    asm volatile(
        "mma.sync.aligned.m16n8k16.row.col.f32.bf16.bf16.f32 "
        "{%0,%1,%2,%3}, {%4,%5,%6,%7}, {%8,%9}, {%0,%1,%2,%3};"
        : "+f"(c[0]), "+f"(c[1]), "+f"(c[2]), "+f"(c[3])
        : "r"(a[0]), "r"(a[1]), "r"(a[2]), "r"(a[3]), "r"(b0), "r"(b1));
}

__device__ __forceinline__ void split1(float v, ushort_t& h, ushort_t& l) {
    __nv_bfloat16 hb = __float2bfloat16(v);
    float r = v - __bfloat162float(hb);
    __nv_bfloat16 lb = __float2bfloat16(r);
    h = __bfloat16_as_ushort(hb);
    l = __bfloat16_as_ushort(lb);
}

// ---------------------------------------------------------------------------
// split fp32 activations -> bf16 hi/lo (row-major passthrough)
// ---------------------------------------------------------------------------
__global__ __launch_bounds__(256) void split_act(
    const float4* __restrict__ x, uint2* __restrict__ hi, uint2* __restrict__ lo, int n4)
{
    int i = blockIdx.x * blockDim.x + threadIdx.x;
    if (i >= n4) return;
    float4 v = x[i];
    ushort_t h0,h1,h2,h3,l0,l1,l2,l3;
    split1(v.x,h0,l0); split1(v.y,h1,l1); split1(v.z,h2,l2); split1(v.w,h3,l3);
    hi[i] = make_uint2((uint32_t)h0 | ((uint32_t)h1 << 16),
                       (uint32_t)h2 | ((uint32_t)h3 << 16));
    lo[i] = make_uint2((uint32_t)l0 | ((uint32_t)l1 << 16),
                       (uint32_t)l2 | ((uint32_t)l3 << 16));
}

// split + transpose W[K][N] -> W^T[N][K] hi/lo
__global__ __launch_bounds__(256) void split_wT(
    const float* __restrict__ W, ushort_t* __restrict__ hi, ushort_t* __restrict__ lo)
{
    __shared__ float t[32][33];
    int n0 = blockIdx.x * 32, k0 = blockIdx.y * 32;
    int tx = threadIdx.x & 31, ty = threadIdx.x >> 5;
    #pragma unroll
    for (int j = 0; j < 4; j++)
        t[ty + 8*j][tx] = W[(size_t)(k0 + ty + 8*j) * DD + n0 + tx];
    __syncthreads();
    #pragma unroll
    for (int j = 0; j < 4; j++) {
        float v = t[tx][ty + 8*j];
        ushort_t h, l; split1(v, h, l);
        size_t o = (size_t)(n0 + ty + 8*j) * DD + k0 + tx;
        hi[o] = h; lo[o] = l;
    }
}

// ---------------------------------------------------------------------------
// Projection GEMM (HMMA split-3): C[4096,1024] = A * W^T + bias
// A hi/lo row-major [M][K]; B hi/lo row-major [N][K].
// mode 0: fp32 -> Cext.  mode 1: bf16 hi/lo head layout -> Chi/Clo.
// CTA 128x128, BK=32, 8 warps (4M x 2N), warp 32x64.
// ---------------------------------------------------------------------------
#define PJ_TILE  10240            // 128 rows * 40 elems * 2B
#define PJ_STAGE (4*PJ_TILE)      // Ahi|Alo|Bhi|Blo
#define PJ_SMEM  (2*PJ_STAGE)     // 81920

__global__ __launch_bounds__(256) void proj_mma(
    const ushort_t* __restrict__ Ahi, const ushort_t* __restrict__ Alo,
    const ushort_t* __restrict__ Bhi, const ushort_t* __restrict__ Blo,
    const float* __restrict__ bias,
    ushort_t* __restrict__ Chi, ushort_t* __restrict__ Clo,
    float* __restrict__ Cext, int mode)
{
    extern __shared__ char smem[];
    const uint32_t sb = smem_to_u32(smem);
    const int tid = threadIdx.x, lane = tid & 31, wid = tid >> 5;
    const int wm = wid >> 1, wn = wid & 1;
    const int m0 = blockIdx.y * 128, n0 = blockIdx.x * 128;

    const ushort_t* gsrc[4] = {Ahi, Alo, Bhi, Blo};

    auto issue = [&](int stage, int k0) {
        #pragma unroll
        for (int i = 0; i < 8; i++) {
            int cid = i * 256 + tid;
            int t = cid >> 9;                 // tile 0..3
            int idx = cid & 511;
            int r = idx >> 2, c = idx & 3;
            int grow = (t < 2 ? m0 : n0) + r;
            const ushort_t* g = gsrc[t] + (size_t)grow * 1024 + k0 + c * 8;
            cpa16(sb + stage * PJ_STAGE + t * PJ_TILE + r * 80 + c * 16, g);
        }
        CP_COMMIT();
    };

    float acc[2][8][4];
    #pragma unroll
    for (int i = 0; i < 2; i++)
        #pragma unroll
        for (int j = 0; j < 8; j++)
            #pragma unroll
            for (int c = 0; c < 4; c++) acc[i][j][c] = 0.f;

    issue(0, 0);
    for (int kc = 0; kc < 32; kc++) {
        if (kc < 31) { issue((kc + 1) & 1, (kc + 1) * 32); CP_WAIT(1); }
        else CP_WAIT(0);
        __syncthreads();
        const uint32_t s0  = sb + (kc & 1) * PJ_STAGE;
        const uint32_t sAh = s0, sAl = s0 + PJ_TILE;
        const uint32_t sBh = s0 + 2*PJ_TILE, sBl = s0 + 3*PJ_TILE;

        #pragma unroll
        for (int ks = 0; ks < 2; ks++) {
            uint32_t ah[2][4], al[2][4];
            #pragma unroll
            for (int i = 0; i < 2; i++) {
                uint32_t off = (uint32_t)(wm*32 + i*16 + (lane & 15)) * 80
                             + ((lane >> 4) * 16) + ks * 32;
                ldsm4(ah[i], sAh + off);
                ldsm4(al[i], sAl + off);
            }
            uint32_t bh[4][4], bl[4][4];
            #pragma unroll
            for (int j4 = 0; j4 < 4; j4++) {
                uint32_t row = (uint32_t)(wn*64 + j4*16 + (lane & 7) + ((lane & 16) >> 1));
                uint32_t off = row * 80 + ks * 32 + ((lane & 8) << 1);
                ldsm4(bh[j4], sBh + off);
                ldsm4(bl[j4], sBl + off);
            }
            #pragma unroll
            for (int i = 0; i < 2; i++)
                #pragma unroll
                for (int j = 0; j < 8; j++) {
                    int j4 = j >> 1, hh = (j & 1) * 2;
                    mma16816(acc[i][j], ah[i], bh[j4][hh], bh[j4][hh+1]);
                    mma16816(acc[i][j], ah[i], bl[j4][hh], bl[j4][hh+1]);
                    mma16816(acc[i][j], al[i], bh[j4][hh], bh[j4][hh+1]);
                }
        }
        __syncthreads();
    }

    // epilogue
    #pragma unroll
    for (int i = 0; i < 2; i++) {
        int mlo = m0 + wm*32 + i*16 + (lane >> 2);
        #pragma unroll
        for (int half = 0; half < 2; half++) {
            int m = mlo + half * 8;
            int b = m >> 10, s = m & 1023;
            #pragma unroll
            for (int j = 0; j < 8; j++) {
                int col = n0 + wn*64 + j*8 + 2*(lane & 3);
                float v0 = acc[i][j][half*2 + 0] + bias[col];
                float v1 = acc[i][j][half*2 + 1] + bias[col + 1];
                if (mode == 0) {
                    *reinterpret_cast<float2*>(Cext + (size_t)m * 1024 + col)
                        = make_float2(v0, v1);
                } else {
                    int h = col >> 6, hd = col & 63;
                    size_t o = ((size_t)((b << 4) + h) * 1024 + s) * 64 + hd;
                    ushort_t h0,l0,h1,l1;
                    split1(v0, h0, l0); split1(v1, h1, l1);
                    *reinterpret_cast<ushort2*>(Chi + o) = make_ushort2(h0, h1);
                    *reinterpret_cast<ushort2*>(Clo + o) = make_ushort2(l0, l1);
                }
            }
        }
    }
}

// ---------------------------------------------------------------------------
// Scores (HMMA split-3): per (b,h) S[128,128] tile = Q @ K^T * 0.125 -> g_P
// K=64 in one load. smem stride 72 elems (144B rows).
// ---------------------------------------------------------------------------
#define SC_TILE  18432            // 128*72*2
#define SC_SMEM  (4*SC_TILE)      // 73728

__global__ __launch_bounds__(256) void scores_mma()
{
    extern __shared__ char smem[];
    const uint32_t sb = smem_to_u32(smem);
    const int tid = threadIdx.x, lane = tid & 31, wid = tid >> 5;
    const int wm = wid >> 1, wn = wid & 1;
    const int bh = blockIdx.z;
    const int m0 = blockIdx.y * 128, n0 = blockIdx.x * 128;

    const ushort_t* gsrc[4] = {g_Qhi, g_Qlo, g_Khi, g_Klo};

    #pragma unroll
    for (int i = 0; i < 16; i++) {
        int cid = i * 256 + tid;
        int t = cid >> 10;
        int idx = cid & 1023;
        int r = idx >> 3, c = idx & 7;
        int base = (t < 2 ? m0 : n0);
        const ushort_t* g = gsrc[t] + ((size_t)bh * 1024 + base + r) * 64 + c * 8;
        cpa16(sb + t * SC_TILE + r * 144 + c * 16, g);
    }
    CP_COMMIT();
    CP_WAIT(0);
    __syncthreads();

    const uint32_t sQh = sb, sQl = sb + SC_TILE;
    const uint32_t sKh = sb + 2*SC_TILE, sKl = sb + 3*SC_TILE;

    float acc[2][8][4];
    #pragma unroll
    for (int i = 0; i < 2; i++)
        #pragma unroll
        for (int j = 0; j < 8; j++)
            #pragma unroll
            for (int c = 0; c < 4; c++) acc[i][j][c] = 0.f;

    #pragma unroll
    for (int ks = 0; ks < 4; ks++) {
        uint32_t ah[2][4], al[2][4];
        #pragma unroll
        for (int i = 0; i < 2; i++) {
            uint32_t off = (uint32_t)(wm*32 + i*16 + (lane & 15)) * 144
                         + ((lane >> 4) * 16) + ks * 32;
            ldsm4(ah[i], sQh + off);
            ldsm4(al[i], sQl + off);
        }
        uint32_t bh4[4][4], bl4[4][4];
        #pragma unroll
        for (int j4 = 0; j4 < 4; j4++) {
            uint32_t row = (uint32_t)(wn*64 + j4*16 + (lane & 7) + ((lane & 16) >> 1));
            uint32_t off = row * 144 + ks * 32 + ((lane & 8) << 1);
            ldsm4(bh4[j4], sKh + off);
            ldsm4(bl4[j4], sKl + off);
        }
        #pragma unroll
        for (int i = 0; i < 2; i++)
            #pragma unroll
            for (int j = 0; j < 8; j++) {
                int j4 = j >> 1, hh = (j & 1) * 2;
                mma16816(acc[i][j], ah[i], bh4[j4][hh], bh4[j4][hh+1]);
                mma16816(acc[i][j], ah[i], bl4[j4][hh], bl4[j4][hh+1]);
                mma16816(acc[i][j], al[i], bh4[j4][hh], bh4[j4][hh+1]);
            }
    }

    float* Pp = g_P + (size_t)bh * SS * SS;
    #pragma unroll
    for (int i = 0; i < 2; i++) {
        int mlo = m0 + wm*32 + i*16 + (lane >> 2);
        #pragma unroll
        for (int half = 0; half < 2; half++) {
            int m = mlo + half * 8;
            #pragma unroll
            for (int j = 0; j < 8; j++) {
                int col = n0 + wn*64 + j*8 + 2*(lane & 3);
                *reinterpret_cast<float2*>(Pp + (size_t)m * SS + col)
                    = make_float2(acc[i][j][half*2+0] * 0.125f,
                                  acc[i][j][half*2+1] * 0.125f);
            }
        }
    }
}

// ---------------------------------------------------------------------------
// Softmax per (b,q) row across all heads; emits P hi/lo bf16 + attn_c.
// ---------------------------------------------------------------------------
__global__ __launch_bounds__(256) void softmax_attnc(
    const float* __restrict__ Wc, const float* __restrict__ bcp,
    float* __restrict__ attn_out)
{
    const int b = blockIdx.x >> 10;
    const int q = blockIdx.x & 1023;
    const int tid = threadIdx.x;
    const int lane = tid & 31, wrp = tid >> 5;

    __shared__ float red[8];
    __shared__ float bcast;

    float acc0 = 0.f, acc1 = 0.f, acc2 = 0.f, acc3 = 0.f;

    for (int h = 0; h < HH; h++) {
        size_t rowoff = ((size_t)((b << 4) + h) * SS + q) * SS;
        const float* row = g_P + rowoff;
        float4 v = *reinterpret_cast<const float4*>(row + (tid << 2));

        float m = fmaxf(fmaxf(v.x, v.y), fmaxf(v.z, v.w));
        #pragma unroll
        for (int o = 16; o; o >>= 1) m = fmaxf(m, __shfl_xor_sync(0xffffffffu, m, o));
        if (lane == 0) red[wrp] = m;
        __syncthreads();
        if (tid == 0) {
            float r = red[0];
            #pragma unroll
            for (int i = 1; i < 8; i++) r = fmaxf(r, red[i]);
            bcast = r;
        }
        __syncthreads();
        m = bcast;

        float e0 = expf(v.x - m), e1 = expf(v.y - m);
        float e2 = expf(v.z - m), e3 = expf(v.w - m);

        float s = e0 + e1 + e2 + e3;
        #pragma unroll
        for (int o = 16; o; o >>= 1) s += __shfl_xor_sync(0xffffffffu, s, o);
        __syncthreads();
        if (lane == 0) red[wrp] = s;
        __syncthreads();
        if (tid == 0) {
            float r = 0.f;
            #pragma unroll
            for (int i = 0; i < 8; i++) r += red[i];
            bcast = r;
        }
        __syncthreads();
        float inv = 1.f / bcast;
        __syncthreads();

        float p0 = e0 * inv, p1 = e1 * inv, p2 = e2 * inv, p3 = e3 * inv;

        ushort_t h0,l0,h1,l1,h2,l2,h3,l3;
        split1(p0,h0,l0); split1(p1,h1,l1); split1(p2,h2,l2); split1(p3,h3,l3);
        uint2 hv = make_uint2((uint32_t)h0 | ((uint32_t)h1 << 16),
                              (uint32_t)h2 | ((uint32_t)h3 << 16));
        uint2 lv = make_uint2((uint32_t)l0 | ((uint32_t)l1 << 16),
                              (uint32_t)l2 | ((uint32_t)l3 << 16));
        *reinterpret_cast<uint2*>(g_Phi + rowoff + (tid << 2)) = hv;
        *reinterpret_cast<uint2*>(g_Plo + rowoff + (tid << 2)) = lv;

        float w = Wc[h];
        acc0 = fmaf(w, p0, acc0); acc1 = fmaf(w, p1, acc1);
        acc2 = fmaf(w, p2, acc2); acc3 = fmaf(w, p3, acc3);
    }

    float bcv = bcp[0];
    *reinterpret_cast<float4*>(attn_out + ((size_t)b * SS + q) * SS + (tid << 2))
        = make_float4(acc0 + bcv, acc1 + bcv, acc2 + bcv, acc3 + bcv);
}

// ---------------------------------------------------------------------------
// PV (HMMA split-3): per (b,h) X[128,64] tile = P @ V -> g_Xhi/g_Xlo [b,s,d]
// P A-side row-major; V consumed via ldmatrix.trans (smem [k][n]).
// CTA 128x64, BK=32, 8 warps (4M x 2N), warp 32x32.
// ---------------------------------------------------------------------------
#define PV_PTILE 10240            // 128*40*2
#define PV_VTILE 4608             // 32*72*2
#define PV_STAGE (2*PV_PTILE + 2*PV_VTILE)   // 29696
#define PV_SMEM  (2*PV_STAGE)                // 59392

__global__ __launch_bounds__(256) void pv_mma()
{
    extern __shared__ char smem[];
    const uint32_t sb = smem_to_u32(smem);
    const int tid = threadIdx.x, lane = tid & 31, wid = tid >> 5;
    const int wm = wid >> 1, wn = wid & 1;
    const int bh = blockIdx.y;
    const int m0 = blockIdx.x * 128;
    const int b = bh >> 4, h = bh & 15;

    auto issue = [&](int stage, int k0) {
        uint32_t s0 = sb + stage * PV_STAGE;
        #pragma unroll
        for (int i = 0; i < 6; i++) {
            int cid = i * 256 + tid;
            if (cid < 1024) {                      // P hi/lo: 2 x 512 chunks
                int t = cid >> 9;                  // 0 hi, 1 lo
                int idx = cid & 511;
                int r = idx >> 2, c = idx & 3;
                const ushort_t* g = (t ? g_Plo : g_Phi)
                    + ((size_t)bh * 1024 + m0 + r) * 1024 + k0 + c * 8;
                cpa16(s0 + t * PV_PTILE + r * 80 + c * 16, g);
            } else {                               // V hi/lo: 2 x 256 chunks
                int cc = cid - 1024;
                int t = cc >> 8;
                int idx = cc & 255;
                int r = idx >> 3, c = idx & 7;
                const ushort_t* g = (t ? g_Vlo : g_Vhi)
                    + ((size_t)bh * 1024 + k0 + r) * 64 + c * 8;
                cpa16(s0 + 2 * PV_PTILE + t * PV_VTILE + r * 144 + c * 16, g);
            }
        }
        CP_COMMIT();
    };

    float acc[2][4][4];
    #pragma unroll
    for (int i = 0; i < 2; i++)
        #pragma unroll
        for (int j = 0; j < 4; j++)
            #pragma unroll
            for (int c = 0; c < 4; c++) acc[i][j][c] = 0.f;

    issue(0, 0);
    for (int kc = 0; kc < 32; kc++) {
        if (kc < 31) { issue((kc + 1) & 1, (kc + 1) * 32); CP_WAIT(1); }
        else CP_WAIT(0);
        __syncthreads();
        const uint32_t s0  = sb + (kc & 1) * PV_STAGE;
        const uint32_t sPh = s0, sPl = s0 + PV_PTILE;
        const uint32_t sVh = s0 + 2*PV_PTILE, sVl = sVh + PV_VTILE;

        #pragma unroll
        for (int ks = 0; ks < 2; ks++) {
            uint32_t ah[2][4], al[2][4];
            #pragma unroll
            for (int i = 0; i < 2; i++) {
                uint32_t off = (uint32_t)(wm*32 + i*16 + (lane & 15)) * 80
                             + ((lane >> 4) * 16) + ks * 32;
                ldsm4(ah[i], sPh + off);
                ldsm4(al[i], sPl + off);
            }
            uint32_t bh2[2][4], bl2[2][4];
            #pragma unroll
            for (int j2 = 0; j2 < 2; j2++) {
                uint32_t row = (uint32_t)(ks*16 + (lane & 7) + ((lane & 8) ? 8 : 0));
                uint32_t col = (uint32_t)(wn*32 + j2*16 + ((lane & 16) ? 8 : 0));
                uint32_t off = row * 144 + col * 2;
                ldsm4t(bh2[j2], sVh + off);
                ldsm4t(bl2[j2], sVl + off);
            }
            #pragma unroll
            for (int i = 0; i < 2; i++)
                #pragma unroll
                for (int j = 0; j < 4; j++) {
                    int j2 = j >> 1, hh = (j & 1) * 2;
                    mma16816(acc[i][j], ah[i], bh2[j2][hh], bh2[j2][hh+1]);
                    mma16816(acc[i][j], ah[i], bl2[j2][hh], bl2[j2][hh+1]);
                    mma16816(acc[i][j], al[i], bh2[j2][hh], bh2[j2][hh+1]);
                }
        }
        __syncthreads();
    }

    #pragma unroll
    for (int i = 0; i < 2; i++) {
        int qlo = m0 + wm*32 + i*16 + (lane >> 2);
        #pragma unroll
        for (int half = 0; half < 2; half++) {
            int q = qlo + half * 8;
            #pragma unroll
            for (int j = 0; j < 4; j++) {
                int hd = wn*32 + j*8 + 2*(lane & 3);
                float v0 = acc[i][j][half*2 + 0];
                float v1 = acc[i][j][half*2 + 1];
                size_t o = ((size_t)(b * 1024 + q)) * 1024 + h * 64 + hd;
                ushort_t h0,l0,h1,l1;
                split1(v0, h0, l0); split1(v1, h1, l1);
                *reinterpret_cast<ushort2*>(g_Xhi + o) = make_ushort2(h0, h1);
                *reinterpret_cast<ushort2*>(g_Xlo + o) = make_ushort2(l0, l1);
            }
        }
    }
}

// ---------------------------------------------------------------------------
extern "C" void kernel_launch(void* const* d_in, const int* in_sizes, int n_in,
                              void* d_out, int out_size)
{
    (void)in_sizes; (void)n_in; (void)out_size;
    const float* query = (const float*)d_in[0];
    const float* key   = (const float*)d_in[1];
    const float* value = (const float*)d_in[2];
    const float* Wq = (const float*)d_in[3];  const float* bq = (const float*)d_in[4];
    const float* Wk = (const float*)d_in[5];  const float* bk = (const float*)d_in[6];
    const float* Wv = (const float*)d_in[7];  const float* bv = (const float*)d_in[8];
    const float* Wo = (const float*)d_in[9];  const float* bo = (const float*)d_in[10];
    const float* Wc = (const float*)d_in[11]; const float* bc = (const float*)d_in[12];

    float* out = (float*)d_out;
    float* attn_out = out + (size_t)BB * SS * DD;

    static bool attr_done = false;
    if (!attr_done) {
        cudaFuncSetAttribute(proj_mma,   cudaFuncAttributeMaxDynamicSharedMemorySize, PJ_SMEM);
        cudaFuncSetAttribute(scores_mma, cudaFuncAttributeMaxDynamicSharedMemorySize, SC_SMEM);
        cudaFuncSetAttribute(pv_mma,     cudaFuncAttributeMaxDynamicSharedMemorySize, PV_SMEM);
        attr_done = true;
    }

    ushort_t *Ahi, *Alo, *Bhi, *Blo, *Qhi, *Qlo, *Khi, *Klo, *Vhi, *Vlo, *Xhi, *Xlo;
    cudaGetSymbolAddress((void**)&Ahi, g_Ahi); cudaGetSymbolAddress((void**)&Alo, g_Alo);
    cudaGetSymbolAddress((void**)&Bhi, g_Bhi); cudaGetSymbolAddress((void**)&Blo, g_Blo);
    cudaGetSymbolAddress((void**)&Qhi, g_Qhi); cudaGetSymbolAddress((void**)&Qlo, g_Qlo);
    cudaGetSymbolAddress((void**)&Khi, g_Khi); cudaGetSymbolAddress((void**)&Klo, g_Klo);
    cudaGetSymbolAddress((void**)&Vhi, g_Vhi); cudaGetSymbolAddress((void**)&Vlo, g_Vlo);
    cudaGetSymbolAddress((void**)&Xhi, g_Xhi); cudaGetSymbolAddress((void**)&Xlo, g_Xlo);

    const int NACT4 = BB * SS * DD / 4;
    dim3 pgrid(8, 32);       // N/128, M/128
    dim3 wgrid(32, 32);

    // Q projection
    split_act<<<NACT4/256, 256>>>((const float4*)query, (uint2*)Ahi, (uint2*)Alo, NACT4);
    split_wT<<<wgrid, 256>>>(Wq, Bhi, Blo);
    proj_mma<<<pgrid, 256, PJ_SMEM>>>(Ahi, Alo, Bhi, Blo, bq, Qhi, Qlo, nullptr, 1);
    // K projection
    split_act<<<NACT4/256, 256>>>((const float4*)key, (uint2*)Ahi, (uint2*)Alo, NACT4);
    split_wT<<<wgrid, 256>>>(Wk, Bhi, Blo);
    proj_mma<<<pgrid, 256, PJ_SMEM>>>(Ahi, Alo, Bhi, Blo, bk, Khi, Klo, nullptr, 1);
    // V projection
    split_act<<<NACT4/256, 256>>>((const float4*)value, (uint2*)Ahi, (uint2*)Alo, NACT4);
    split_wT<<<wgrid, 256>>>(Wv, Bhi, Blo);
    proj_mma<<<pgrid, 256, PJ_SMEM>>>(Ahi, Alo, Bhi, Blo, bv, Vhi, Vlo, nullptr, 1);

    // scores -> g_P
    scores_mma<<<dim3(8, 8, BB*HH), 256, SC_SMEM>>>();

    // softmax -> Phi/Plo + attn_c
    softmax_attnc<<<BB * SS, 256>>>(Wc, bc, attn_out);

    // PV -> Xhi/Xlo
    pv_mma<<<dim3(8, BB*HH), 256, PV_SMEM>>>();

    // out projection (A = Xhi/Xlo directly)
    split_wT<<<wgrid, 256>>>(Wo, Bhi, Blo);
    proj_mma<<<pgrid, 256, PJ_SMEM>>>(Xhi, Xlo, Bhi, Blo, bo, nullptr, nullptr, out, 0);
}

// round 6
// speedup vs baseline: 3.3461x; 1.1308x over previous
#include <cuda_runtime.h>
#include <cuda_bf16.h>
#include <cuda_fp16.h>
#include <math.h>
#include <stdint.h>

#define BB 4
#define SS 1024
#define DD 1024
#define HH 16
#define HD 64

typedef unsigned short ushort_t;

__device__ float    g_P [(size_t)BB*HH*SS*SS];    // fp32 scores (256MB)
__device__ __half   g_Pf[(size_t)BB*HH*SS*SS];    // probs fp16 (128MB)
__device__ __half   g_Qf[BB*HH*SS*HD];
__device__ __half   g_Kf[BB*HH*SS*HD];
__device__ __half   g_Vf[BB*HH*SS*HD];
__device__ ushort_t g_Xhi[BB*SS*DD], g_Xlo[BB*SS*DD];
__device__ ushort_t g_Ahi[BB*SS*DD], g_Alo[BB*SS*DD];
__device__ ushort_t g_Bhi[DD*DD],    g_Blo[DD*DD];

// ---------------- helpers ----------------
__device__ __forceinline__ uint32_t smem_to_u32(const void* p) {
    uint32_t a;
    asm("{ .reg .u64 t; cvta.to.shared.u64 t, %1; cvt.u32.u64 %0, t; }"
        : "=r"(a) : "l"(p));
    return a;
}
__device__ __forceinline__ void cpa16(uint32_t s, const void* g) {
    asm volatile("cp.async.cg.shared.global [%0], [%1], 16;" :: "r"(s), "l"(g));
}
#define CP_COMMIT() asm volatile("cp.async.commit_group;")
#define CP_WAIT(n)  asm volatile("cp.async.wait_group %0;" :: "n"(n))

__device__ __forceinline__ void ldsm4(uint32_t* r, uint32_t addr) {
    asm volatile("ldmatrix.sync.aligned.m8n8.x4.shared.b16 {%0,%1,%2,%3}, [%4];"
        : "=r"(r[0]), "=r"(r[1]), "=r"(r[2]), "=r"(r[3]) : "r"(addr));
}
__device__ __forceinline__ void ldsm4t(uint32_t* r, uint32_t addr) {
    asm volatile("ldmatrix.sync.aligned.m8n8.x4.trans.shared.b16 {%0,%1,%2,%3}, [%4];"
        : "=r"(r[0]), "=r"(r[1]), "=r"(r[2]), "=r"(r[3]) : "r"(addr));
}
__device__ __forceinline__ void mma16816(float* c, const uint32_t* a,
                                         uint32_t b0, uint32_t b1) {
    asm volatile(
        "mma.sync.aligned.m16n8k16.row.col.f32.bf16.bf16.f32 "
        "{%0,%1,%2,%3}, {%4,%5,%6,%7}, {%8,%9}, {%0,%1,%2,%3};"
        : "+f"(c[0]), "+f"(c[1]), "+f"(c[2]), "+f"(c[3])
        : "r"(a[0]), "r"(a[1]), "r"(a[2]), "r"(a[3]), "r"(b0), "r"(b1));
}
__device__ __forceinline__ void mma16816h(float* c, const uint32_t* a,
                                          uint32_t b0, uint32_t b1) {
    asm volatile(
        "mma.sync.aligned.m16n8k16.row.col.f32.f16.f16.f32 "
        "{%0,%1,%2,%3}, {%4,%5,%6,%7}, {%8,%9}, {%0,%1,%2,%3};"
        : "+f"(c[0]), "+f"(c[1]), "+f"(c[2]), "+f"(c[3])
        : "r"(a[0]), "r"(a[1]), "r"(a[2]), "r"(a[3]), "r"(b0), "r"(b1));
}
__device__ __forceinline__ void split1(float v, ushort_t& h, ushort_t& l) {
    __nv_bfloat16 hb = __float2bfloat16(v);
    float r = v - __bfloat162float(hb);
    __nv_bfloat16 lb = __float2bfloat16(r);
    h = __bfloat16_as_ushort(hb);
    l = __bfloat16_as_ushort(lb);
}

// ---------------- splits ----------------
__global__ __launch_bounds__(256) void split_act(
    const float4* __restrict__ x, uint2* __restrict__ hi, uint2* __restrict__ lo, int n4)
{
    int i = blockIdx.x * blockDim.x + threadIdx.x;
    if (i >= n4) return;
    float4 v = x[i];
    ushort_t h0,h1,h2,h3,l0,l1,l2,l3;
    split1(v.x,h0,l0); split1(v.y,h1,l1); split1(v.z,h2,l2); split1(v.w,h3,l3);
    hi[i] = make_uint2((uint32_t)h0 | ((uint32_t)h1 << 16),
                       (uint32_t)h2 | ((uint32_t)h3 << 16));
    lo[i] = make_uint2((uint32_t)l0 | ((uint32_t)l1 << 16),
                       (uint32_t)l2 | ((uint32_t)l3 << 16));
}

__global__ __launch_bounds__(256) void split_wT(
    const float* __restrict__ W, ushort_t* __restrict__ hi, ushort_t* __restrict__ lo)
{
    __shared__ float t[32][33];
    int n0 = blockIdx.x * 32, k0 = blockIdx.y * 32;
    int tx = threadIdx.x & 31, ty = threadIdx.x >> 5;
    #pragma unroll
    for (int j = 0; j < 4; j++)
        t[ty + 8*j][tx] = W[(size_t)(k0 + ty + 8*j) * DD + n0 + tx];
    __syncthreads();
    #pragma unroll
    for (int j = 0; j < 4; j++) {
        float v = t[tx][ty + 8*j];
        ushort_t h, l; split1(v, h, l);
        size_t o = (size_t)(n0 + ty + 8*j) * DD + k0 + tx;
        hi[o] = h; lo[o] = l;
    }
}

// ---------------- projection GEMM (bf16 split-3, exact) ----------------
// mode 0: fp32 -> Cext.  mode 1: fp16 head layout -> Cf.
#define PJ_TILE  10240
#define PJ_STAGE (4*PJ_TILE)
#define PJ_SMEM  (2*PJ_STAGE)

__global__ __launch_bounds__(256) void proj_mma(
    const ushort_t* __restrict__ Ahi, const ushort_t* __restrict__ Alo,
    const ushort_t* __restrict__ Bhi, const ushort_t* __restrict__ Blo,
    const float* __restrict__ bias,
    __half* __restrict__ Cf, float* __restrict__ Cext, int mode)
{
    extern __shared__ char smem[];
    const uint32_t sb = smem_to_u32(smem);
    const int tid = threadIdx.x, lane = tid & 31, wid = tid >> 5;
    const int wm = wid >> 1, wn = wid & 1;
    const int m0 = blockIdx.y * 128, n0 = blockIdx.x * 128;

    const ushort_t* gsrc[4] = {Ahi, Alo, Bhi, Blo};

    auto issue = [&](int stage, int k0) {
        #pragma unroll
        for (int i = 0; i < 8; i++) {
            int cid = i * 256 + tid;
            int t = cid >> 9;
            int idx = cid & 511;
            int r = idx >> 2, c = idx & 3;
            int grow = (t < 2 ? m0 : n0) + r;
            const ushort_t* g = gsrc[t] + (size_t)grow * 1024 + k0 + c * 8;
            cpa16(sb + stage * PJ_STAGE + t * PJ_TILE + r * 80 + c * 16, g);
        }
        CP_COMMIT();
    };

    float acc[2][8][4];
    #pragma unroll
    for (int i = 0; i < 2; i++)
        #pragma unroll
        for (int j = 0; j < 8; j++)
            #pragma unroll
            for (int c = 0; c < 4; c++) acc[i][j][c] = 0.f;

    issue(0, 0);
    for (int kc = 0; kc < 32; kc++) {
        if (kc < 31) { issue((kc + 1) & 1, (kc + 1) * 32); CP_WAIT(1); }
        else CP_WAIT(0);
        __syncthreads();
        const uint32_t s0  = sb + (kc & 1) * PJ_STAGE;
        const uint32_t sAh = s0, sAl = s0 + PJ_TILE;
        const uint32_t sBh = s0 + 2*PJ_TILE, sBl = s0 + 3*PJ_TILE;

        #pragma unroll
        for (int ks = 0; ks < 2; ks++) {
            uint32_t ah[2][4], al[2][4];
            #pragma unroll
            for (int i = 0; i < 2; i++) {
                uint32_t off = (uint32_t)(wm*32 + i*16 + (lane & 15)) * 80
                             + ((lane >> 4) * 16) + ks * 32;
                ldsm4(ah[i], sAh + off);
                ldsm4(al[i], sAl + off);
            }
            uint32_t bh[4][4], bl[4][4];
            #pragma unroll
            for (int j4 = 0; j4 < 4; j4++) {
                uint32_t row = (uint32_t)(wn*64 + j4*16 + (lane & 7) + ((lane & 16) >> 1));
                uint32_t off = row * 80 + ks * 32 + ((lane & 8) << 1);
                ldsm4(bh[j4], sBh + off);
                ldsm4(bl[j4], sBl + off);
            }
            #pragma unroll
            for (int i = 0; i < 2; i++)
                #pragma unroll
                for (int j = 0; j < 8; j++) {
                    int j4 = j >> 1, hh = (j & 1) * 2;
                    mma16816(acc[i][j], ah[i], bh[j4][hh], bh[j4][hh+1]);
                    mma16816(acc[i][j], ah[i], bl[j4][hh], bl[j4][hh+1]);
                    mma16816(acc[i][j], al[i], bh[j4][hh], bh[j4][hh+1]);
                }
        }
        __syncthreads();
    }

    #pragma unroll
    for (int i = 0; i < 2; i++) {
        int mlo = m0 + wm*32 + i*16 + (lane >> 2);
        #pragma unroll
        for (int half = 0; half < 2; half++) {
            int m = mlo + half * 8;
            int b = m >> 10, s = m & 1023;
            #pragma unroll
            for (int j = 0; j < 8; j++) {
                int col = n0 + wn*64 + j*8 + 2*(lane & 3);
                float v0 = acc[i][j][half*2 + 0] + bias[col];
                float v1 = acc[i][j][half*2 + 1] + bias[col + 1];
                if (mode == 0) {
                    *reinterpret_cast<float2*>(Cext + (size_t)m * 1024 + col)
                        = make_float2(v0, v1);
                } else {
                    int h = col >> 6, hd = col & 63;
                    size_t o = ((size_t)((b << 4) + h) * 1024 + s) * 64 + hd;
                    *reinterpret_cast<__half2*>(Cf + o) = __floats2half2_rn(v0, v1);
                }
            }
        }
    }
}

// ---------------- scores (single fp16 MMA) ----------------
#define SC_TILE  18432            // 128 rows * 72 elems * 2B
#define SC_SMEM  (2*SC_TILE)

__global__ __launch_bounds__(256) void scores_mma()
{
    extern __shared__ char smem[];
    const uint32_t sb = smem_to_u32(smem);
    const int tid = threadIdx.x, lane = tid & 31, wid = tid >> 5;
    const int wm = wid >> 1, wn = wid & 1;
    const int bh = blockIdx.z;
    const int m0 = blockIdx.y * 128, n0 = blockIdx.x * 128;

    #pragma unroll
    for (int i = 0; i < 8; i++) {
        int cid = i * 256 + tid;
        int t = cid >> 10;                 // 0 = Q, 1 = K
        int idx = cid & 1023;
        int r = idx >> 3, c = idx & 7;
        int base = (t == 0 ? m0 : n0);
        const __half* g = (t == 0 ? g_Qf : g_Kf)
            + ((size_t)bh * 1024 + base + r) * 64 + c * 8;
        cpa16(sb + t * SC_TILE + r * 144 + c * 16, g);
    }
    CP_COMMIT();
    CP_WAIT(0);
    __syncthreads();

    const uint32_t sQ = sb, sK = sb + SC_TILE;

    float acc[2][8][4];
    #pragma unroll
    for (int i = 0; i < 2; i++)
        #pragma unroll
        for (int j = 0; j < 8; j++)
            #pragma unroll
            for (int c = 0; c < 4; c++) acc[i][j][c] = 0.f;

    #pragma unroll
    for (int ks = 0; ks < 4; ks++) {
        uint32_t a[2][4];
        #pragma unroll
        for (int i = 0; i < 2; i++) {
            uint32_t off = (uint32_t)(wm*32 + i*16 + (lane & 15)) * 144
                         + ((lane >> 4) * 16) + ks * 32;
            ldsm4(a[i], sQ + off);
        }
        uint32_t b4[4][4];
        #pragma unroll
        for (int j4 = 0; j4 < 4; j4++) {
            uint32_t row = (uint32_t)(wn*64 + j4*16 + (lane & 7) + ((lane & 16) >> 1));
            uint32_t off = row * 144 + ks * 32 + ((lane & 8) << 1);
            ldsm4(b4[j4], sK + off);
        }
        #pragma unroll
        for (int i = 0; i < 2; i++)
            #pragma unroll
            for (int j = 0; j < 8; j++) {
                int j4 = j >> 1, hh = (j & 1) * 2;
                mma16816h(acc[i][j], a[i], b4[j4][hh], b4[j4][hh+1]);
            }
    }

    float* Pp = g_P + (size_t)bh * SS * SS;
    #pragma unroll
    for (int i = 0; i < 2; i++) {
        int mlo = m0 + wm*32 + i*16 + (lane >> 2);
        #pragma unroll
        for (int half = 0; half < 2; half++) {
            int m = mlo + half * 8;
            #pragma unroll
            for (int j = 0; j < 8; j++) {
                int col = n0 + wn*64 + j*8 + 2*(lane & 3);
                *reinterpret_cast<float2*>(Pp + (size_t)m * SS + col)
                    = make_float2(acc[i][j][half*2+0] * 0.125f,
                                  acc[i][j][half*2+1] * 0.125f);
            }
        }
    }
}

// ---------------- softmax + attn_c (P out as fp16) ----------------
__global__ __launch_bounds__(256) void softmax_attnc(
    const float* __restrict__ Wc, const float* __restrict__ bcp,
    float* __restrict__ attn_out)
{
    const int b = blockIdx.x >> 10;
    const int q = blockIdx.x & 1023;
    const int tid = threadIdx.x;
    const int lane = tid & 31, wrp = tid >> 5;

    __shared__ float red[8];
    __shared__ float bcast;

    float acc0 = 0.f, acc1 = 0.f, acc2 = 0.f, acc3 = 0.f;

    for (int h = 0; h < HH; h++) {
        size_t rowoff = ((size_t)((b << 4) + h) * SS + q) * SS;
        const float* row = g_P + rowoff;
        float4 v = *reinterpret_cast<const float4*>(row + (tid << 2));

        float m = fmaxf(fmaxf(v.x, v.y), fmaxf(v.z, v.w));
        #pragma unroll
        for (int o = 16; o; o >>= 1) m = fmaxf(m, __shfl_xor_sync(0xffffffffu, m, o));
        if (lane == 0) red[wrp] = m;
        __syncthreads();
        if (tid == 0) {
            float r = red[0];
            #pragma unroll
            for (int i = 1; i < 8; i++) r = fmaxf(r, red[i]);
            bcast = r;
        }
        __syncthreads();
        m = bcast;

        float e0 = expf(v.x - m), e1 = expf(v.y - m);
        float e2 = expf(v.z - m), e3 = expf(v.w - m);

        float s = e0 + e1 + e2 + e3;
        #pragma unroll
        for (int o = 16; o; o >>= 1) s += __shfl_xor_sync(0xffffffffu, s, o);
        __syncthreads();
        if (lane == 0) red[wrp] = s;
        __syncthreads();
        if (tid == 0) {
            float r = 0.f;
            #pragma unroll
            for (int i = 0; i < 8; i++) r += red[i];
            bcast = r;
        }
        __syncthreads();
        float inv = 1.f / bcast;
        __syncthreads();

        float p0 = e0 * inv, p1 = e1 * inv, p2 = e2 * inv, p3 = e3 * inv;

        __half2 q0 = __floats2half2_rn(p0, p1);
        __half2 q1 = __floats2half2_rn(p2, p3);
        *reinterpret_cast<uint2*>(g_Pf + rowoff + (tid << 2))
            = make_uint2(*reinterpret_cast<uint32_t*>(&q0),
                         *reinterpret_cast<uint32_t*>(&q1));

        float w = Wc[h];
        acc0 = fmaf(w, p0, acc0); acc1 = fmaf(w, p1, acc1);
        acc2 = fmaf(w, p2, acc2); acc3 = fmaf(w, p3, acc3);
    }

    float bcv = bcp[0];
    *reinterpret_cast<float4*>(attn_out + ((size_t)b * SS + q) * SS + (tid << 2))
        = make_float4(acc0 + bcv, acc1 + bcv, acc2 + bcv, acc3 + bcv);
}

// ---------------- PV (single fp16 MMA) ----------------
#define PV_PTILE 10240            // 128*40*2
#define PV_VTILE 4608             // 32*72*2
#define PV_STAGE (PV_PTILE + PV_VTILE)   // 14848
#define PV_SMEM  (2*PV_STAGE)

__global__ __launch_bounds__(256) void pv_mma()
{
    extern __shared__ char smem[];
    const uint32_t sb = smem_to_u32(smem);
    const int tid = threadIdx.x, lane = tid & 31, wid = tid >> 5;
    const int wm = wid >> 1, wn = wid & 1;
    const int bh = blockIdx.y;
    const int m0 = blockIdx.x * 128;
    const int b = bh >> 4, h = bh & 15;

    auto issue = [&](int stage, int k0) {
        uint32_t s0 = sb + stage * PV_STAGE;
        #pragma unroll
        for (int i = 0; i < 3; i++) {
            int cid = i * 256 + tid;
            if (cid < 512) {                       // P: 512 chunks
                int r = cid >> 2, c = cid & 3;
                const __half* g = g_Pf
                    + ((size_t)bh * 1024 + m0 + r) * 1024 + k0 + c * 8;
                cpa16(s0 + r * 80 + c * 16, g);
            } else {                               // V: 256 chunks
                int idx = cid - 512;
                int r = idx >> 3, c = idx & 7;
                const __half* g = g_Vf
                    + ((size_t)bh * 1024 + k0 + r) * 64 + c * 8;
                cpa16(s0 + PV_PTILE + r * 144 + c * 16, g);
            }
        }
        CP_COMMIT();
    };

    float acc[2][4][4];
    #pragma unroll
    for (int i = 0; i < 2; i++)
        #pragma unroll
        for (int j = 0; j < 4; j++)
            #pragma unroll
            for (int c = 0; c < 4; c++) acc[i][j][c] = 0.f;

    issue(0, 0);
    for (int kc = 0; kc < 32; kc++) {
        if (kc < 31) { issue((kc + 1) & 1, (kc + 1) * 32); CP_WAIT(1); }
        else CP_WAIT(0);
        __syncthreads();
        const uint32_t s0 = sb + (kc & 1) * PV_STAGE;
        const uint32_t sP = s0, sV = s0 + PV_PTILE;

        #pragma unroll
        for (int ks = 0; ks < 2; ks++) {
            uint32_t a[2][4];
            #pragma unroll
            for (int i = 0; i < 2; i++) {
                uint32_t off = (uint32_t)(wm*32 + i*16 + (lane & 15)) * 80
                             + ((lane >> 4) * 16) + ks * 32;
                ldsm4(a[i], sP + off);
            }
            uint32_t b2[2][4];
            #pragma unroll
            for (int j2 = 0; j2 < 2; j2++) {
                uint32_t row = (uint32_t)(ks*16 + (lane & 7) + ((lane & 8) ? 8 : 0));
                uint32_t col = (uint32_t)(wn*32 + j2*16 + ((lane & 16) ? 8 : 0));
                ldsm4t(b2[j2], sV + row * 144 + col * 2);
            }
            #pragma unroll
            for (int i = 0; i < 2; i++)
                #pragma unroll
                for (int j = 0; j < 4; j++) {
                    int j2 = j >> 1, hh = (j & 1) * 2;
                    mma16816h(acc[i][j], a[i], b2[j2][hh], b2[j2][hh+1]);
                }
        }
        __syncthreads();
    }

    #pragma unroll
    for (int i = 0; i < 2; i++) {
        int qlo = m0 + wm*32 + i*16 + (lane >> 2);
        #pragma unroll
        for (int half = 0; half < 2; half++) {
            int q = qlo + half * 8;
            #pragma unroll
            for (int j = 0; j < 4; j++) {
                int hd = wn*32 + j*8 + 2*(lane & 3);
                float v0 = acc[i][j][half*2 + 0];
                float v1 = acc[i][j][half*2 + 1];
                size_t o = ((size_t)(b * 1024 + q)) * 1024 + h * 64 + hd;
                ushort_t h0,l0,h1,l1;
                split1(v0, h0, l0); split1(v1, h1, l1);
                *reinterpret_cast<ushort2*>(g_Xhi + o) = make_ushort2(h0, h1);
                *reinterpret_cast<ushort2*>(g_Xlo + o) = make_ushort2(l0, l1);
            }
        }
    }
}

// ---------------------------------------------------------------------------
extern "C" void kernel_launch(void* const* d_in, const int* in_sizes, int n_in,
                              void* d_out, int out_size)
{
    (void)in_sizes; (void)n_in; (void)out_size;
    const float* query = (const float*)d_in[0];
    const float* key   = (const float*)d_in[1];
    const float* value = (const float*)d_in[2];
    const float* Wq = (const float*)d_in[3];  const float* bq = (const float*)d_in[4];
    const float* Wk = (const float*)d_in[5];  const float* bk = (const float*)d_in[6];
    const float* Wv = (const float*)d_in[7];  const float* bv = (const float*)d_in[8];
    const float* Wo = (const float*)d_in[9];  const float* bo = (const float*)d_in[10];
    const float* Wc = (const float*)d_in[11]; const float* bc = (const float*)d_in[12];

    float* out = (float*)d_out;
    float* attn_out = out + (size_t)BB * SS * DD;

    static bool attr_done = false;
    if (!attr_done) {
        cudaFuncSetAttribute(proj_mma,   cudaFuncAttributeMaxDynamicSharedMemorySize, PJ_SMEM);
        cudaFuncSetAttribute(scores_mma, cudaFuncAttributeMaxDynamicSharedMemorySize, SC_SMEM);
        cudaFuncSetAttribute(pv_mma,     cudaFuncAttributeMaxDynamicSharedMemorySize, PV_SMEM);
        attr_done = true;
    }

    ushort_t *Ahi, *Alo, *Bhi, *Blo, *Xhi, *Xlo;
    __half *Qf, *Kf, *Vf;
    cudaGetSymbolAddress((void**)&Ahi, g_Ahi); cudaGetSymbolAddress((void**)&Alo, g_Alo);
    cudaGetSymbolAddress((void**)&Bhi, g_Bhi); cudaGetSymbolAddress((void**)&Blo, g_Blo);
    cudaGetSymbolAddress((void**)&Qf, g_Qf);   cudaGetSymbolAddress((void**)&Kf, g_Kf);
    cudaGetSymbolAddress((void**)&Vf, g_Vf);
    cudaGetSymbolAddress((void**)&Xhi, g_Xhi); cudaGetSymbolAddress((void**)&Xlo, g_Xlo);

    const int NACT4 = BB * SS * DD / 4;
    dim3 pgrid(8, 32);
    dim3 wgrid(32, 32);

    split_act<<<NACT4/256, 256>>>((const float4*)query, (uint2*)Ahi, (uint2*)Alo, NACT4);
    split_wT<<<wgrid, 256>>>(Wq, Bhi, Blo);
    proj_mma<<<pgrid, 256, PJ_SMEM>>>(Ahi, Alo, Bhi, Blo, bq, Qf, nullptr, 1);

    split_act<<<NACT4/256, 256>>>((const float4*)key, (uint2*)Ahi, (uint2*)Alo, NACT4);
    split_wT<<<wgrid, 256>>>(Wk, Bhi, Blo);
    proj_mma<<<pgrid, 256, PJ_SMEM>>>(Ahi, Alo, Bhi, Blo, bk, Kf, nullptr, 1);

    split_act<<<NACT4/256, 256>>>((const float4*)value, (uint2*)Ahi, (uint2*)Alo, NACT4);
    split_wT<<<wgrid, 256>>>(Wv, Bhi, Blo);
    proj_mma<<<pgrid, 256, PJ_SMEM>>>(Ahi, Alo, Bhi, Blo, bv, Vf, nullptr, 1);

    scores_mma<<<dim3(8, 8, BB*HH), 256, SC_SMEM>>>();
    softmax_attnc<<<BB * SS, 256>>>(Wc, bc, attn_out);
    pv_mma<<<dim3(8, BB*HH), 256, PV_SMEM>>>();

    split_wT<<<wgrid, 256>>>(Wo, Bhi, Blo);
    proj_mma<<<pgrid, 256, PJ_SMEM>>>(Xhi, Xlo, Bhi, Blo, bo, nullptr, out, 0);
}

// round 7
// speedup vs baseline: 4.0125x; 1.1992x over previous
#include <cuda_runtime.h>
#include <cuda_bf16.h>
#include <cuda_fp16.h>
#include <math.h>
#include <stdint.h>

#define BB 4
#define SS 1024
#define DD 1024
#define HH 16
#define HD 64

typedef unsigned short ushort_t;

__device__ float    g_P [(size_t)BB*HH*SS*SS];    // fp32 scores (256MB)
__device__ __half   g_Pf[(size_t)BB*HH*SS*SS];    // probs fp16 (128MB)
__device__ __half   g_Qf[BB*HH*SS*HD];
__device__ __half   g_Kf[BB*HH*SS*HD];
__device__ __half   g_Vf[BB*HH*SS*HD];
__device__ ushort_t g_Xhi[BB*SS*DD], g_Xlo[BB*SS*DD];  // X fp16 hi/lo planes
__device__ ushort_t g_Ahi[BB*SS*DD], g_Alo[BB*SS*DD];  // activation fp16 hi/lo
__device__ ushort_t g_Bf [DD*DD];                      // W^T fp16 single plane

// ---------------- helpers ----------------
__device__ __forceinline__ uint32_t smem_to_u32(const void* p) {
    uint32_t a;
    asm("{ .reg .u64 t; cvta.to.shared.u64 t, %1; cvt.u32.u64 %0, t; }"
        : "=r"(a) : "l"(p));
    return a;
}
__device__ __forceinline__ void cpa16(uint32_t s, const void* g) {
    asm volatile("cp.async.cg.shared.global [%0], [%1], 16;" :: "r"(s), "l"(g));
}
#define CP_COMMIT() asm volatile("cp.async.commit_group;")
#define CP_WAIT(n)  asm volatile("cp.async.wait_group %0;" :: "n"(n))

__device__ __forceinline__ void ldsm4(uint32_t* r, uint32_t addr) {
    asm volatile("ldmatrix.sync.aligned.m8n8.x4.shared.b16 {%0,%1,%2,%3}, [%4];"
        : "=r"(r[0]), "=r"(r[1]), "=r"(r[2]), "=r"(r[3]) : "r"(addr));
}
__device__ __forceinline__ void ldsm4t(uint32_t* r, uint32_t addr) {
    asm volatile("ldmatrix.sync.aligned.m8n8.x4.trans.shared.b16 {%0,%1,%2,%3}, [%4];"
        : "=r"(r[0]), "=r"(r[1]), "=r"(r[2]), "=r"(r[3]) : "r"(addr));
}
__device__ __forceinline__ void mma16816h(float* c, const uint32_t* a,
                                          uint32_t b0, uint32_t b1) {
    asm volatile(
        "mma.sync.aligned.m16n8k16.row.col.f32.f16.f16.f32 "
        "{%0,%1,%2,%3}, {%4,%5,%6,%7}, {%8,%9}, {%0,%1,%2,%3};"
        : "+f"(c[0]), "+f"(c[1]), "+f"(c[2]), "+f"(c[3])
        : "r"(a[0]), "r"(a[1]), "r"(a[2]), "r"(a[3]), "r"(b0), "r"(b1));
}
__device__ __forceinline__ void split1h(float v, ushort_t& h, ushort_t& l) {
    __half hb = __float2half_rn(v);
    float r = v - __half2float(hb);
    __half lb = __float2half_rn(r);
    h = __half_as_ushort(hb);
    l = __half_as_ushort(lb);
}

// ---------------- splits ----------------
__global__ __launch_bounds__(256) void split_act_h(
    const float4* __restrict__ x, uint2* __restrict__ hi, uint2* __restrict__ lo, int n4)
{
    int i = blockIdx.x * blockDim.x + threadIdx.x;
    if (i >= n4) return;
    float4 v = x[i];
    ushort_t h0,h1,h2,h3,l0,l1,l2,l3;
    split1h(v.x,h0,l0); split1h(v.y,h1,l1); split1h(v.z,h2,l2); split1h(v.w,h3,l3);
    hi[i] = make_uint2((uint32_t)h0 | ((uint32_t)h1 << 16),
                       (uint32_t)h2 | ((uint32_t)h3 << 16));
    lo[i] = make_uint2((uint32_t)l0 | ((uint32_t)l1 << 16),
                       (uint32_t)l2 | ((uint32_t)l3 << 16));
}

// transpose W[K][N] -> W^T[N][K], single fp16 plane
__global__ __launch_bounds__(256) void split_wT_h(
    const float* __restrict__ W, ushort_t* __restrict__ bf)
{
    __shared__ float t[32][33];
    int n0 = blockIdx.x * 32, k0 = blockIdx.y * 32;
    int tx = threadIdx.x & 31, ty = threadIdx.x >> 5;
    #pragma unroll
    for (int j = 0; j < 4; j++)
        t[ty + 8*j][tx] = W[(size_t)(k0 + ty + 8*j) * DD + n0 + tx];
    __syncthreads();
    #pragma unroll
    for (int j = 0; j < 4; j++) {
        float v = t[tx][ty + 8*j];
        bf[(size_t)(n0 + ty + 8*j) * DD + k0 + tx]
            = __half_as_ushort(__float2half_rn(v));
    }
}

// ---------------- projection GEMM (fp16 split-2) ----------------
// C = (Ahi + Alo) * B^T + bias ; A planes fp16, B single fp16 [N][K].
// mode 0: fp32 -> Cext.  mode 1: fp16 head layout -> Cf.
#define PJ_TILE  10240            // 128 rows * 40 elems * 2B
#define PJ_STAGE (3*PJ_TILE)      // Ahi|Alo|B
#define PJ_SMEM  (2*PJ_STAGE)     // 61440

__global__ __launch_bounds__(256) void proj_mma2(
    const ushort_t* __restrict__ Ahi, const ushort_t* __restrict__ Alo,
    const ushort_t* __restrict__ Bf,
    const float* __restrict__ bias,
    __half* __restrict__ Cf, float* __restrict__ Cext, int mode)
{
    extern __shared__ char smem[];
    const uint32_t sb = smem_to_u32(smem);
    const int tid = threadIdx.x, lane = tid & 31, wid = tid >> 5;
    const int wm = wid >> 1, wn = wid & 1;
    const int m0 = blockIdx.y * 128, n0 = blockIdx.x * 128;

    const ushort_t* gsrc[3] = {Ahi, Alo, Bf};

    auto issue = [&](int stage, int k0) {
        #pragma unroll
        for (int i = 0; i < 6; i++) {
            int cid = i * 256 + tid;
            int t = cid >> 9;                 // 0 Ahi, 1 Alo, 2 B
            int idx = cid & 511;
            int r = idx >> 2, c = idx & 3;
            int grow = (t < 2 ? m0 : n0) + r;
            const ushort_t* g = gsrc[t] + (size_t)grow * 1024 + k0 + c * 8;
            cpa16(sb + stage * PJ_STAGE + t * PJ_TILE + r * 80 + c * 16, g);
        }
        CP_COMMIT();
    };

    float acc[2][8][4];
    #pragma unroll
    for (int i = 0; i < 2; i++)
        #pragma unroll
        for (int j = 0; j < 8; j++)
            #pragma unroll
            for (int c = 0; c < 4; c++) acc[i][j][c] = 0.f;

    issue(0, 0);
    for (int kc = 0; kc < 32; kc++) {
        if (kc < 31) { issue((kc + 1) & 1, (kc + 1) * 32); CP_WAIT(1); }
        else CP_WAIT(0);
        __syncthreads();
        const uint32_t s0  = sb + (kc & 1) * PJ_STAGE;
        const uint32_t sAh = s0, sAl = s0 + PJ_TILE, sB = s0 + 2*PJ_TILE;

        #pragma unroll
        for (int ks = 0; ks < 2; ks++) {
            uint32_t ah[2][4], al[2][4];
            #pragma unroll
            for (int i = 0; i < 2; i++) {
                uint32_t off = (uint32_t)(wm*32 + i*16 + (lane & 15)) * 80
                             + ((lane >> 4) * 16) + ks * 32;
                ldsm4(ah[i], sAh + off);
                ldsm4(al[i], sAl + off);
            }
            uint32_t b4[4][4];
            #pragma unroll
            for (int j4 = 0; j4 < 4; j4++) {
                uint32_t row = (uint32_t)(wn*64 + j4*16 + (lane & 7) + ((lane & 16) >> 1));
                uint32_t off = row * 80 + ks * 32 + ((lane & 8) << 1);
                ldsm4(b4[j4], sB + off);
            }
            #pragma unroll
            for (int i = 0; i < 2; i++)
                #pragma unroll
                for (int j = 0; j < 8; j++) {
                    int j4 = j >> 1, hh = (j & 1) * 2;
                    mma16816h(acc[i][j], ah[i], b4[j4][hh], b4[j4][hh+1]);
                    mma16816h(acc[i][j], al[i], b4[j4][hh], b4[j4][hh+1]);
                }
        }
        __syncthreads();
    }

    #pragma unroll
    for (int i = 0; i < 2; i++) {
        int mlo = m0 + wm*32 + i*16 + (lane >> 2);
        #pragma unroll
        for (int half = 0; half < 2; half++) {
            int m = mlo + half * 8;
            int b = m >> 10, s = m & 1023;
            #pragma unroll
            for (int j = 0; j < 8; j++) {
                int col = n0 + wn*64 + j*8 + 2*(lane & 3);
                float v0 = acc[i][j][half*2 + 0] + bias[col];
                float v1 = acc[i][j][half*2 + 1] + bias[col + 1];
                if (mode == 0) {
                    *reinterpret_cast<float2*>(Cext + (size_t)m * 1024 + col)
                        = make_float2(v0, v1);
                } else {
                    int h = col >> 6, hd = col & 63;
                    size_t o = ((size_t)((b << 4) + h) * 1024 + s) * 64 + hd;
                    *reinterpret_cast<__half2*>(Cf + o) = __floats2half2_rn(v0, v1);
                }
            }
        }
    }
}

// ---------------- scores (single fp16 MMA) ----------------
#define SC_TILE  18432            // 128 rows * 72 elems * 2B
#define SC_SMEM  (2*SC_TILE)

__global__ __launch_bounds__(256) void scores_mma()
{
    extern __shared__ char smem[];
    const uint32_t sb = smem_to_u32(smem);
    const int tid = threadIdx.x, lane = tid & 31, wid = tid >> 5;
    const int wm = wid >> 1, wn = wid & 1;
    const int bh = blockIdx.z;
    const int m0 = blockIdx.y * 128, n0 = blockIdx.x * 128;

    #pragma unroll
    for (int i = 0; i < 8; i++) {
        int cid = i * 256 + tid;
        int t = cid >> 10;                 // 0 = Q, 1 = K
        int idx = cid & 1023;
        int r = idx >> 3, c = idx & 7;
        int base = (t == 0 ? m0 : n0);
        const __half* g = (t == 0 ? g_Qf : g_Kf)
            + ((size_t)bh * 1024 + base + r) * 64 + c * 8;
        cpa16(sb + t * SC_TILE + r * 144 + c * 16, g);
    }
    CP_COMMIT();
    CP_WAIT(0);
    __syncthreads();

    const uint32_t sQ = sb, sK = sb + SC_TILE;

    float acc[2][8][4];
    #pragma unroll
    for (int i = 0; i < 2; i++)
        #pragma unroll
        for (int j = 0; j < 8; j++)
            #pragma unroll
            for (int c = 0; c < 4; c++) acc[i][j][c] = 0.f;

    #pragma unroll
    for (int ks = 0; ks < 4; ks++) {
        uint32_t a[2][4];
        #pragma unroll
        for (int i = 0; i < 2; i++) {
            uint32_t off = (uint32_t)(wm*32 + i*16 + (lane & 15)) * 144
                         + ((lane >> 4) * 16) + ks * 32;
            ldsm4(a[i], sQ + off);
        }
        uint32_t b4[4][4];
        #pragma unroll
        for (int j4 = 0; j4 < 4; j4++) {
            uint32_t row = (uint32_t)(wn*64 + j4*16 + (lane & 7) + ((lane & 16) >> 1));
            uint32_t off = row * 144 + ks * 32 + ((lane & 8) << 1);
            ldsm4(b4[j4], sK + off);
        }
        #pragma unroll
        for (int i = 0; i < 2; i++)
            #pragma unroll
            for (int j = 0; j < 8; j++) {
                int j4 = j >> 1, hh = (j & 1) * 2;
                mma16816h(acc[i][j], a[i], b4[j4][hh], b4[j4][hh+1]);
            }
    }

    float* Pp = g_P + (size_t)bh * SS * SS;
    #pragma unroll
    for (int i = 0; i < 2; i++) {
        int mlo = m0 + wm*32 + i*16 + (lane >> 2);
        #pragma unroll
        for (int half = 0; half < 2; half++) {
            int m = mlo + half * 8;
            #pragma unroll
            for (int j = 0; j < 8; j++) {
                int col = n0 + wn*64 + j*8 + 2*(lane & 3);
                *reinterpret_cast<float2*>(Pp + (size_t)m * SS + col)
                    = make_float2(acc[i][j][half*2+0] * 0.125f,
                                  acc[i][j][half*2+1] * 0.125f);
            }
        }
    }
}

// ---------------- softmax + attn_c (P out as fp16) ----------------
__global__ __launch_bounds__(256) void softmax_attnc(
    const float* __restrict__ Wc, const float* __restrict__ bcp,
    float* __restrict__ attn_out)
{
    const int b = blockIdx.x >> 10;
    const int q = blockIdx.x & 1023;
    const int tid = threadIdx.x;
    const int lane = tid & 31, wrp = tid >> 5;

    __shared__ float red[8];
    __shared__ float bcast;

    float acc0 = 0.f, acc1 = 0.f, acc2 = 0.f, acc3 = 0.f;

    for (int h = 0; h < HH; h++) {
        size_t rowoff = ((size_t)((b << 4) + h) * SS + q) * SS;
        const float* row = g_P + rowoff;
        float4 v = *reinterpret_cast<const float4*>(row + (tid << 2));

        float m = fmaxf(fmaxf(v.x, v.y), fmaxf(v.z, v.w));
        #pragma unroll
        for (int o = 16; o; o >>= 1) m = fmaxf(m, __shfl_xor_sync(0xffffffffu, m, o));
        if (lane == 0) red[wrp] = m;
        __syncthreads();
        if (tid == 0) {
            float r = red[0];
            #pragma unroll
            for (int i = 1; i < 8; i++) r = fmaxf(r, red[i]);
            bcast = r;
        }
        __syncthreads();
        m = bcast;

        float e0 = expf(v.x - m), e1 = expf(v.y - m);
        float e2 = expf(v.z - m), e3 = expf(v.w - m);

        float s = e0 + e1 + e2 + e3;
        #pragma unroll
        for (int o = 16; o; o >>= 1) s += __shfl_xor_sync(0xffffffffu, s, o);
        __syncthreads();
        if (lane == 0) red[wrp] = s;
        __syncthreads();
        if (tid == 0) {
            float r = 0.f;
            #pragma unroll
            for (int i = 0; i < 8; i++) r += red[i];
            bcast = r;
        }
        __syncthreads();
        float inv = 1.f / bcast;
        __syncthreads();

        float p0 = e0 * inv, p1 = e1 * inv, p2 = e2 * inv, p3 = e3 * inv;

        __half2 q0 = __floats2half2_rn(p0, p1);
        __half2 q1 = __floats2half2_rn(p2, p3);
        *reinterpret_cast<uint2*>(g_Pf + rowoff + (tid << 2))
            = make_uint2(*reinterpret_cast<uint32_t*>(&q0),
                         *reinterpret_cast<uint32_t*>(&q1));

        float w = Wc[h];
        acc0 = fmaf(w, p0, acc0); acc1 = fmaf(w, p1, acc1);
        acc2 = fmaf(w, p2, acc2); acc3 = fmaf(w, p3, acc3);
    }

    float bcv = bcp[0];
    *reinterpret_cast<float4*>(attn_out + ((size_t)b * SS + q) * SS + (tid << 2))
        = make_float4(acc0 + bcv, acc1 + bcv, acc2 + bcv, acc3 + bcv);
}

// ---------------- PV (single fp16 MMA; X out fp16 hi/lo) ----------------
#define PV_PTILE 10240            // 128*40*2
#define PV_VTILE 4608             // 32*72*2
#define PV_STAGE (PV_PTILE + PV_VTILE)   // 14848
#define PV_SMEM  (2*PV_STAGE)

__global__ __launch_bounds__(256) void pv_mma()
{
    extern __shared__ char smem[];
    const uint32_t sb = smem_to_u32(smem);
    const int tid = threadIdx.x, lane = tid & 31, wid = tid >> 5;
    const int wm = wid >> 1, wn = wid & 1;
    const int bh = blockIdx.y;
    const int m0 = blockIdx.x * 128;
    const int b = bh >> 4, h = bh & 15;

    auto issue = [&](int stage, int k0) {
        uint32_t s0 = sb + stage * PV_STAGE;
        #pragma unroll
        for (int i = 0; i < 3; i++) {
            int cid = i * 256 + tid;
            if (cid < 512) {
                int r = cid >> 2, c = cid & 3;
                const __half* g = g_Pf
                    + ((size_t)bh * 1024 + m0 + r) * 1024 + k0 + c * 8;
                cpa16(s0 + r * 80 + c * 16, g);
            } else {
                int idx = cid - 512;
                int r = idx >> 3, c = idx & 7;
                const __half* g = g_Vf
                    + ((size_t)bh * 1024 + k0 + r) * 64 + c * 8;
                cpa16(s0 + PV_PTILE + r * 144 + c * 16, g);
            }
        }
        CP_COMMIT();
    };

    float acc[2][4][4];
    #pragma unroll
    for (int i = 0; i < 2; i++)
        #pragma unroll
        for (int j = 0; j < 4; j++)
            #pragma unroll
            for (int c = 0; c < 4; c++) acc[i][j][c] = 0.f;

    issue(0, 0);
    for (int kc = 0; kc < 32; kc++) {
        if (kc < 31) { issue((kc + 1) & 1, (kc + 1) * 32); CP_WAIT(1); }
        else CP_WAIT(0);
        __syncthreads();
        const uint32_t s0 = sb + (kc & 1) * PV_STAGE;
        const uint32_t sP = s0, sV = s0 + PV_PTILE;

        #pragma unroll
        for (int ks = 0; ks < 2; ks++) {
            uint32_t a[2][4];
            #pragma unroll
            for (int i = 0; i < 2; i++) {
                uint32_t off = (uint32_t)(wm*32 + i*16 + (lane & 15)) * 80
                             + ((lane >> 4) * 16) + ks * 32;
                ldsm4(a[i], sP + off);
            }
            uint32_t b2[2][4];
            #pragma unroll
            for (int j2 = 0; j2 < 2; j2++) {
                uint32_t row = (uint32_t)(ks*16 + (lane & 7) + ((lane & 8) ? 8 : 0));
                uint32_t col = (uint32_t)(wn*32 + j2*16 + ((lane & 16) ? 8 : 0));
                ldsm4t(b2[j2], sV + row * 144 + col * 2);
            }
            #pragma unroll
            for (int i = 0; i < 2; i++)
                #pragma unroll
                for (int j = 0; j < 4; j++) {
                    int j2 = j >> 1, hh = (j & 1) * 2;
                    mma16816h(acc[i][j], a[i], b2[j2][hh], b2[j2][hh+1]);
                }
        }
        __syncthreads();
    }

    #pragma unroll
    for (int i = 0; i < 2; i++) {
        int qlo = m0 + wm*32 + i*16 + (lane >> 2);
        #pragma unroll
        for (int half = 0; half < 2; half++) {
            int q = qlo + half * 8;
            #pragma unroll
            for (int j = 0; j < 4; j++) {
                int hd = wn*32 + j*8 + 2*(lane & 3);
                float v0 = acc[i][j][half*2 + 0];
                float v1 = acc[i][j][half*2 + 1];
                size_t o = ((size_t)(b * 1024 + q)) * 1024 + h * 64 + hd;
                ushort_t h0,l0,h1,l1;
                split1h(v0, h0, l0); split1h(v1, h1, l1);
                *reinterpret_cast<ushort2*>(g_Xhi + o) = make_ushort2(h0, h1);
                *reinterpret_cast<ushort2*>(g_Xlo + o) = make_ushort2(l0, l1);
            }
        }
    }
}

// ---------------------------------------------------------------------------
extern "C" void kernel_launch(void* const* d_in, const int* in_sizes, int n_in,
                              void* d_out, int out_size)
{
    (void)in_sizes; (void)n_in; (void)out_size;
    const float* query = (const float*)d_in[0];
    const float* key   = (const float*)d_in[1];
    const float* value = (const float*)d_in[2];
    const float* Wq = (const float*)d_in[3];  const float* bq = (const float*)d_in[4];
    const float* Wk = (const float*)d_in[5];  const float* bk = (const float*)d_in[6];
    const float* Wv = (const float*)d_in[7];  const float* bv = (const float*)d_in[8];
    const float* Wo = (const float*)d_in[9];  const float* bo = (const float*)d_in[10];
    const float* Wc = (const float*)d_in[11]; const float* bc = (const float*)d_in[12];

    float* out = (float*)d_out;
    float* attn_out = out + (size_t)BB * SS * DD;

    static bool attr_done = false;
    if (!attr_done) {
        cudaFuncSetAttribute(proj_mma2,  cudaFuncAttributeMaxDynamicSharedMemorySize, PJ_SMEM);
        cudaFuncSetAttribute(scores_mma, cudaFuncAttributeMaxDynamicSharedMemorySize, SC_SMEM);
        cudaFuncSetAttribute(pv_mma,     cudaFuncAttributeMaxDynamicSharedMemorySize, PV_SMEM);
        attr_done = true;
    }

    ushort_t *Ahi, *Alo, *Bf, *Xhi, *Xlo;
    __half *Qf, *Kf, *Vf;
    cudaGetSymbolAddress((void**)&Ahi, g_Ahi); cudaGetSymbolAddress((void**)&Alo, g_Alo);
    cudaGetSymbolAddress((void**)&Bf, g_Bf);
    cudaGetSymbolAddress((void**)&Qf, g_Qf);   cudaGetSymbolAddress((void**)&Kf, g_Kf);
    cudaGetSymbolAddress((void**)&Vf, g_Vf);
    cudaGetSymbolAddress((void**)&Xhi, g_Xhi); cudaGetSymbolAddress((void**)&Xlo, g_Xlo);

    const int NACT4 = BB * SS * DD / 4;
    dim3 pgrid(8, 32);
    dim3 wgrid(32, 32);

    split_act_h<<<NACT4/256, 256>>>((const float4*)query, (uint2*)Ahi, (uint2*)Alo, NACT4);
    split_wT_h<<<wgrid, 256>>>(Wq, Bf);
    proj_mma2<<<pgrid, 256, PJ_SMEM>>>(Ahi, Alo, Bf, bq, Qf, nullptr, 1);

    split_act_h<<<NACT4/256, 256>>>((const float4*)key, (uint2*)Ahi, (uint2*)Alo, NACT4);
    split_wT_h<<<wgrid, 256>>>(Wk, Bf);
    proj_mma2<<<pgrid, 256, PJ_SMEM>>>(Ahi, Alo, Bf, bk, Kf, nullptr, 1);

    split_act_h<<<NACT4/256, 256>>>((const float4*)value, (uint2*)Ahi, (uint2*)Alo, NACT4);
    split_wT_h<<<wgrid, 256>>>(Wv, Bf);
    proj_mma2<<<pgrid, 256, PJ_SMEM>>>(Ahi, Alo, Bf, bv, Vf, nullptr, 1);

    scores_mma<<<dim3(8, 8, BB*HH), 256, SC_SMEM>>>();
    softmax_attnc<<<BB * SS, 256>>>(Wc, bc, attn_out);
    pv_mma<<<dim3(8, BB*HH), 256, PV_SMEM>>>();

    split_wT_h<<<wgrid, 256>>>(Wo, Bf);
    proj_mma2<<<pgrid, 256, PJ_SMEM>>>(Xhi, Xlo, Bf, bo, nullptr, out, 0);
}

// round 8
// speedup vs baseline: 4.4287x; 1.1037x over previous
#include <cuda_runtime.h>
#include <cuda_bf16.h>
#include <cuda_fp16.h>
#include <math.h>
#include <stdint.h>

#define BB 4
#define SS 1024
#define DD 1024
#define HH 16
#define HD 64

typedef unsigned short ushort_t;

#define NACT (BB*SS*DD)           // 4M elements per activation plane

__device__ float    g_P [(size_t)BB*HH*SS*SS];    // fp32 scores (256MB)
__device__ __half   g_Pf[(size_t)BB*HH*SS*SS];    // probs fp16 (128MB)
__device__ __half   g_Qf[BB*HH*SS*HD];
__device__ __half   g_Kf[BB*HH*SS*HD];
__device__ __half   g_Vf[BB*HH*SS*HD];
__device__ ushort_t g_Xhi[NACT], g_Xlo[NACT];     // X fp16 hi/lo planes
__device__ ushort_t g_Ahi[3*NACT], g_Alo[3*NACT]; // q/k/v activation fp16 hi/lo
__device__ ushort_t g_Bf [4*DD*DD];               // W^T fp16: q,k,v,o planes

// ---------------- helpers ----------------
__device__ __forceinline__ uint32_t smem_to_u32(const void* p) {
    uint32_t a;
    asm("{ .reg .u64 t; cvta.to.shared.u64 t, %1; cvt.u32.u64 %0, t; }"
        : "=r"(a) : "l"(p));
    return a;
}
__device__ __forceinline__ void cpa16(uint32_t s, const void* g) {
    asm volatile("cp.async.cg.shared.global [%0], [%1], 16;" :: "r"(s), "l"(g));
}
#define CP_COMMIT() asm volatile("cp.async.commit_group;")
#define CP_WAIT(n)  asm volatile("cp.async.wait_group %0;" :: "n"(n))

__device__ __forceinline__ void ldsm4(uint32_t* r, uint32_t addr) {
    asm volatile("ldmatrix.sync.aligned.m8n8.x4.shared.b16 {%0,%1,%2,%3}, [%4];"
        : "=r"(r[0]), "=r"(r[1]), "=r"(r[2]), "=r"(r[3]) : "r"(addr));
}
__device__ __forceinline__ void ldsm4t(uint32_t* r, uint32_t addr) {
    asm volatile("ldmatrix.sync.aligned.m8n8.x4.trans.shared.b16 {%0,%1,%2,%3}, [%4];"
        : "=r"(r[0]), "=r"(r[1]), "=r"(r[2]), "=r"(r[3]) : "r"(addr));
}
__device__ __forceinline__ void mma16816h(float* c, const uint32_t* a,
                                          uint32_t b0, uint32_t b1) {
    asm volatile(
        "mma.sync.aligned.m16n8k16.row.col.f32.f16.f16.f32 "
        "{%0,%1,%2,%3}, {%4,%5,%6,%7}, {%8,%9}, {%0,%1,%2,%3};"
        : "+f"(c[0]), "+f"(c[1]), "+f"(c[2]), "+f"(c[3])
        : "r"(a[0]), "r"(a[1]), "r"(a[2]), "r"(a[3]), "r"(b0), "r"(b1));
}
__device__ __forceinline__ void split1h(float v, ushort_t& h, ushort_t& l) {
    __half hb = __float2half_rn(v);
    float r = v - __half2float(hb);
    __half lb = __float2half_rn(r);
    h = __half_as_ushort(hb);
    l = __half_as_ushort(lb);
}

// ---------------- splits (merged launches) ----------------
// grid (N/256, 3): z picks which activation input and which plane.
__global__ __launch_bounds__(256) void split_act3(
    const float4* __restrict__ x0, const float4* __restrict__ x1,
    const float4* __restrict__ x2)
{
    const int z = blockIdx.y;
    const float4* x = (z == 0) ? x0 : (z == 1) ? x1 : x2;
    uint2* hi = reinterpret_cast<uint2*>(g_Ahi) + (size_t)z * (NACT/4);
    uint2* lo = reinterpret_cast<uint2*>(g_Alo) + (size_t)z * (NACT/4);
    int i = blockIdx.x * blockDim.x + threadIdx.x;
    float4 v = x[i];
    ushort_t h0,h1,h2,h3,l0,l1,l2,l3;
    split1h(v.x,h0,l0); split1h(v.y,h1,l1); split1h(v.z,h2,l2); split1h(v.w,h3,l3);
    hi[i] = make_uint2((uint32_t)h0 | ((uint32_t)h1 << 16),
                       (uint32_t)h2 | ((uint32_t)h3 << 16));
    lo[i] = make_uint2((uint32_t)l0 | ((uint32_t)l1 << 16),
                       (uint32_t)l2 | ((uint32_t)l3 << 16));
}

// transpose W[K][N] -> W^T[N][K] fp16; grid (32,32,4), z picks weight.
__global__ __launch_bounds__(256) void split_wT4(
    const float* __restrict__ W0, const float* __restrict__ W1,
    const float* __restrict__ W2, const float* __restrict__ W3)
{
    const int z = blockIdx.z;
    const float* W = (z == 0) ? W0 : (z == 1) ? W1 : (z == 2) ? W2 : W3;
    ushort_t* bf = g_Bf + (size_t)z * DD * DD;
    __shared__ float t[32][33];
    int n0 = blockIdx.x * 32, k0 = blockIdx.y * 32;
    int tx = threadIdx.x & 31, ty = threadIdx.x >> 5;
    #pragma unroll
    for (int j = 0; j < 4; j++)
        t[ty + 8*j][tx] = W[(size_t)(k0 + ty + 8*j) * DD + n0 + tx];
    __syncthreads();
    #pragma unroll
    for (int j = 0; j < 4; j++) {
        float v = t[tx][ty + 8*j];
        bf[(size_t)(n0 + ty + 8*j) * DD + k0 + tx]
            = __half_as_ushort(__float2half_rn(v));
    }
}

// ---------------- projection GEMM (fp16 split-2) ----------------
#define PJ_TILE  10240            // 128 rows * 40 elems * 2B
#define PJ_STAGE (3*PJ_TILE)      // Ahi|Alo|B
#define PJ_SMEM  (2*PJ_STAGE)     // 61440

// shared mainloop; writes acc via epilogue flag.
struct ProjOut {
    __half* Cf;        // head layout if non-null
    float*  Cext;      // plain fp32 if non-null
};

__device__ __forceinline__ void proj_core(
    const ushort_t* __restrict__ Ahi, const ushort_t* __restrict__ Alo,
    const ushort_t* __restrict__ Bf, const float* __restrict__ bias,
    __half* __restrict__ Cf, float* __restrict__ Cext,
    char* smem, int m0, int n0)
{
    const uint32_t sb = smem_to_u32(smem);
    const int tid = threadIdx.x, lane = tid & 31, wid = tid >> 5;
    const int wm = wid >> 1, wn = wid & 1;

    const ushort_t* gsrc[3] = {Ahi, Alo, Bf};

    auto issue = [&](int stage, int k0) {
        #pragma unroll
        for (int i = 0; i < 6; i++) {
            int cid = i * 256 + tid;
            int t = cid >> 9;
            int idx = cid & 511;
            int r = idx >> 2, c = idx & 3;
            int grow = (t < 2 ? m0 : n0) + r;
            const ushort_t* g = gsrc[t] + (size_t)grow * 1024 + k0 + c * 8;
            cpa16(sb + stage * PJ_STAGE + t * PJ_TILE + r * 80 + c * 16, g);
        }
        CP_COMMIT();
    };

    float acc[2][8][4];
    #pragma unroll
    for (int i = 0; i < 2; i++)
        #pragma unroll
        for (int j = 0; j < 8; j++)
            #pragma unroll
            for (int c = 0; c < 4; c++) acc[i][j][c] = 0.f;

    issue(0, 0);
    for (int kc = 0; kc < 32; kc++) {
        if (kc < 31) { issue((kc + 1) & 1, (kc + 1) * 32); CP_WAIT(1); }
        else CP_WAIT(0);
        __syncthreads();
        const uint32_t s0  = sb + (kc & 1) * PJ_STAGE;
        const uint32_t sAh = s0, sAl = s0 + PJ_TILE, sB = s0 + 2*PJ_TILE;

        #pragma unroll
        for (int ks = 0; ks < 2; ks++) {
            uint32_t ah[2][4], al[2][4];
            #pragma unroll
            for (int i = 0; i < 2; i++) {
                uint32_t off = (uint32_t)(wm*32 + i*16 + (lane & 15)) * 80
                             + ((lane >> 4) * 16) + ks * 32;
                ldsm4(ah[i], sAh + off);
                ldsm4(al[i], sAl + off);
            }
            uint32_t b4[4][4];
            #pragma unroll
            for (int j4 = 0; j4 < 4; j4++) {
                uint32_t row = (uint32_t)(wn*64 + j4*16 + (lane & 7) + ((lane & 16) >> 1));
                uint32_t off = row * 80 + ks * 32 + ((lane & 8) << 1);
                ldsm4(b4[j4], sB + off);
            }
            #pragma unroll
            for (int i = 0; i < 2; i++)
                #pragma unroll
                for (int j = 0; j < 8; j++) {
                    int j4 = j >> 1, hh = (j & 1) * 2;
                    mma16816h(acc[i][j], ah[i], b4[j4][hh], b4[j4][hh+1]);
                    mma16816h(acc[i][j], al[i], b4[j4][hh], b4[j4][hh+1]);
                }
        }
        __syncthreads();
    }

    #pragma unroll
    for (int i = 0; i < 2; i++) {
        int mlo = m0 + wm*32 + i*16 + (lane >> 2);
        #pragma unroll
        for (int half = 0; half < 2; half++) {
            int m = mlo + half * 8;
            int b = m >> 10, s = m & 1023;
            #pragma unroll
            for (int j = 0; j < 8; j++) {
                int col = n0 + wn*64 + j*8 + 2*(lane & 3);
                float v0 = acc[i][j][half*2 + 0] + bias[col];
                float v1 = acc[i][j][half*2 + 1] + bias[col + 1];
                if (Cext) {
                    *reinterpret_cast<float2*>(Cext + (size_t)m * 1024 + col)
                        = make_float2(v0, v1);
                } else {
                    int h = col >> 6, hd = col & 63;
                    size_t o = ((size_t)((b << 4) + h) * 1024 + s) * 64 + hd;
                    *reinterpret_cast<__half2*>(Cf + o) = __floats2half2_rn(v0, v1);
                }
            }
        }
    }
}

// QKV projections in one launch: grid (8, 32, 3)
__global__ __launch_bounds__(256) void proj_qkv(
    const float* __restrict__ b0, const float* __restrict__ b1,
    const float* __restrict__ b2)
{
    extern __shared__ char smem[];
    const int z = blockIdx.z;
    const ushort_t* Ahi = g_Ahi + (size_t)z * NACT;
    const ushort_t* Alo = g_Alo + (size_t)z * NACT;
    const ushort_t* Bf  = g_Bf  + (size_t)z * DD * DD;
    const float* bias = (z == 0) ? b0 : (z == 1) ? b1 : b2;
    __half* Cf = (z == 0) ? g_Qf : (z == 1) ? g_Kf : g_Vf;
    proj_core(Ahi, Alo, Bf, bias, Cf, nullptr, smem,
              blockIdx.y * 128, blockIdx.x * 128);
}

// out projection: grid (8, 32)
__global__ __launch_bounds__(256) void proj_out(
    const float* __restrict__ bias, float* __restrict__ Cext)
{
    extern __shared__ char smem[];
    proj_core(g_Xhi, g_Xlo, g_Bf + (size_t)3 * DD * DD, bias, nullptr, Cext,
              smem, blockIdx.y * 128, blockIdx.x * 128);
}

// ---------------- scores (single fp16 MMA) ----------------
#define SC_TILE  18432            // 128 rows * 72 elems * 2B
#define SC_SMEM  (2*SC_TILE)

__global__ __launch_bounds__(256) void scores_mma()
{
    extern __shared__ char smem[];
    const uint32_t sb = smem_to_u32(smem);
    const int tid = threadIdx.x, lane = tid & 31, wid = tid >> 5;
    const int wm = wid >> 1, wn = wid & 1;
    const int bh = blockIdx.z;
    const int m0 = blockIdx.y * 128, n0 = blockIdx.x * 128;

    #pragma unroll
    for (int i = 0; i < 8; i++) {
        int cid = i * 256 + tid;
        int t = cid >> 10;
        int idx = cid & 1023;
        int r = idx >> 3, c = idx & 7;
        int base = (t == 0 ? m0 : n0);
        const __half* g = (t == 0 ? g_Qf : g_Kf)
            + ((size_t)bh * 1024 + base + r) * 64 + c * 8;
        cpa16(sb + t * SC_TILE + r * 144 + c * 16, g);
    }
    CP_COMMIT();
    CP_WAIT(0);
    __syncthreads();

    const uint32_t sQ = sb, sK = sb + SC_TILE;

    float acc[2][8][4];
    #pragma unroll
    for (int i = 0; i < 2; i++)
        #pragma unroll
        for (int j = 0; j < 8; j++)
            #pragma unroll
            for (int c = 0; c < 4; c++) acc[i][j][c] = 0.f;

    #pragma unroll
    for (int ks = 0; ks < 4; ks++) {
        uint32_t a[2][4];
        #pragma unroll
        for (int i = 0; i < 2; i++) {
            uint32_t off = (uint32_t)(wm*32 + i*16 + (lane & 15)) * 144
                         + ((lane >> 4) * 16) + ks * 32;
            ldsm4(a[i], sQ + off);
        }
        uint32_t b4[4][4];
        #pragma unroll
        for (int j4 = 0; j4 < 4; j4++) {
            uint32_t row = (uint32_t)(wn*64 + j4*16 + (lane & 7) + ((lane & 16) >> 1));
            uint32_t off = row * 144 + ks * 32 + ((lane & 8) << 1);
            ldsm4(b4[j4], sK + off);
        }
        #pragma unroll
        for (int i = 0; i < 2; i++)
            #pragma unroll
            for (int j = 0; j < 8; j++) {
                int j4 = j >> 1, hh = (j & 1) * 2;
                mma16816h(acc[i][j], a[i], b4[j4][hh], b4[j4][hh+1]);
            }
    }

    float* Pp = g_P + (size_t)bh * SS * SS;
    #pragma unroll
    for (int i = 0; i < 2; i++) {
        int mlo = m0 + wm*32 + i*16 + (lane >> 2);
        #pragma unroll
        for (int half = 0; half < 2; half++) {
            int m = mlo + half * 8;
            #pragma unroll
            for (int j = 0; j < 8; j++) {
                int col = n0 + wn*64 + j*8 + 2*(lane & 3);
                *reinterpret_cast<float2*>(Pp + (size_t)m * SS + col)
                    = make_float2(acc[i][j][half*2+0] * 0.125f,
                                  acc[i][j][half*2+1] * 0.125f);
            }
        }
    }
}

// ---------------- softmax + attn_c (warp-per-row) ----------------
// Block 256 = 8 warps per (b,q). Warp w handles heads w and w+8 with pure
// shfl reductions; one block sync to combine attn_c partials.
__global__ __launch_bounds__(256) void softmax_attnc(
    const float* __restrict__ Wc, const float* __restrict__ bcp,
    float* __restrict__ attn_out)
{
    const int b = blockIdx.x >> 10;
    const int q = blockIdx.x & 1023;
    const int tid = threadIdx.x;
    const int lane = tid & 31, w = tid >> 5;

    __shared__ float part[8][1024];

    float acc[8][4];
    #pragma unroll
    for (int i = 0; i < 8; i++)
        #pragma unroll
        for (int c = 0; c < 4; c++) acc[i][c] = 0.f;

    #pragma unroll
    for (int hi = 0; hi < 2; hi++) {
        const int h = w + hi * 8;
        size_t rowoff = ((size_t)((b << 4) + h) * SS + q) * SS;
        const float* row = g_P + rowoff;

        float4 v[8];
        #pragma unroll
        for (int i = 0; i < 8; i++)
            v[i] = *reinterpret_cast<const float4*>(row + i * 128 + lane * 4);

        float m = -1e30f;
        #pragma unroll
        for (int i = 0; i < 8; i++)
            m = fmaxf(m, fmaxf(fmaxf(v[i].x, v[i].y), fmaxf(v[i].z, v[i].w)));
        #pragma unroll
        for (int o = 16; o; o >>= 1) m = fmaxf(m, __shfl_xor_sync(0xffffffffu, m, o));

        float s = 0.f;
        #pragma unroll
        for (int i = 0; i < 8; i++) {
            v[i].x = expf(v[i].x - m); v[i].y = expf(v[i].y - m);
            v[i].z = expf(v[i].z - m); v[i].w = expf(v[i].w - m);
            s += v[i].x + v[i].y + v[i].z + v[i].w;
        }
        #pragma unroll
        for (int o = 16; o; o >>= 1) s += __shfl_xor_sync(0xffffffffu, s, o);
        const float inv = 1.f / s;
        const float wc = Wc[h];

        #pragma unroll
        for (int i = 0; i < 8; i++) {
            float p0 = v[i].x * inv, p1 = v[i].y * inv;
            float p2 = v[i].z * inv, p3 = v[i].w * inv;
            __half2 q0 = __floats2half2_rn(p0, p1);
            __half2 q1 = __floats2half2_rn(p2, p3);
            *reinterpret_cast<uint2*>(g_Pf + rowoff + i * 128 + lane * 4)
                = make_uint2(*reinterpret_cast<uint32_t*>(&q0),
                             *reinterpret_cast<uint32_t*>(&q1));
            acc[i][0] = fmaf(wc, p0, acc[i][0]);
            acc[i][1] = fmaf(wc, p1, acc[i][1]);
            acc[i][2] = fmaf(wc, p2, acc[i][2]);
            acc[i][3] = fmaf(wc, p3, acc[i][3]);
        }
    }

    #pragma unroll
    for (int i = 0; i < 8; i++)
        *reinterpret_cast<float4*>(&part[w][i * 128 + lane * 4])
            = make_float4(acc[i][0], acc[i][1], acc[i][2], acc[i][3]);
    __syncthreads();

    // 256 threads: each sums one float4 column-group over 8 warps
    {
        const float bcv = bcp[0];
        float4 r = make_float4(bcv, bcv, bcv, bcv);
        #pragma unroll
        for (int ww = 0; ww < 8; ww++) {
            float4 p = *reinterpret_cast<float4*>(&part[ww][tid * 4]);
            r.x += p.x; r.y += p.y; r.z += p.z; r.w += p.w;
        }
        *reinterpret_cast<float4*>(
            attn_out + ((size_t)b * SS + q) * SS + tid * 4) = r;
    }
}

// ---------------- PV (single fp16 MMA; X out fp16 hi/lo) ----------------
#define PV_PTILE 10240            // 128*40*2
#define PV_VTILE 4608             // 32*72*2
#define PV_STAGE (PV_PTILE + PV_VTILE)   // 14848
#define PV_SMEM  (2*PV_STAGE)

__global__ __launch_bounds__(256) void pv_mma()
{
    extern __shared__ char smem[];
    const uint32_t sb = smem_to_u32(smem);
    const int tid = threadIdx.x, lane = tid & 31, wid = tid >> 5;
    const int wm = wid >> 1, wn = wid & 1;
    const int bh = blockIdx.y;
    const int m0 = blockIdx.x * 128;
    const int b = bh >> 4, h = bh & 15;

    auto issue = [&](int stage, int k0) {
        uint32_t s0 = sb + stage * PV_STAGE;
        #pragma unroll
        for (int i = 0; i < 3; i++) {
            int cid = i * 256 + tid;
            if (cid < 512) {
                int r = cid >> 2, c = cid & 3;
                const __half* g = g_Pf
                    + ((size_t)bh * 1024 + m0 + r) * 1024 + k0 + c * 8;
                cpa16(s0 + r * 80 + c * 16, g);
            } else {
                int idx = cid - 512;
                int r = idx >> 3, c = idx & 7;
                const __half* g = g_Vf
                    + ((size_t)bh * 1024 + k0 + r) * 64 + c * 8;
                cpa16(s0 + PV_PTILE + r * 144 + c * 16, g);
            }
        }
        CP_COMMIT();
    };

    float acc[2][4][4];
    #pragma unroll
    for (int i = 0; i < 2; i++)
        #pragma unroll
        for (int j = 0; j < 4; j++)
            #pragma unroll
            for (int c = 0; c < 4; c++) acc[i][j][c] = 0.f;

    issue(0, 0);
    for (int kc = 0; kc < 32; kc++) {
        if (kc < 31) { issue((kc + 1) & 1, (kc + 1) * 32); CP_WAIT(1); }
        else CP_WAIT(0);
        __syncthreads();
        const uint32_t s0 = sb + (kc & 1) * PV_STAGE;
        const uint32_t sP = s0, sV = s0 + PV_PTILE;

        #pragma unroll
        for (int ks = 0; ks < 2; ks++) {
            uint32_t a[2][4];
            #pragma unroll
            for (int i = 0; i < 2; i++) {
                uint32_t off = (uint32_t)(wm*32 + i*16 + (lane & 15)) * 80
                             + ((lane >> 4) * 16) + ks * 32;
                ldsm4(a[i], sP + off);
            }
            uint32_t b2[2][4];
            #pragma unroll
            for (int j2 = 0; j2 < 2; j2++) {
                uint32_t row = (uint32_t)(ks*16 + (lane & 7) + ((lane & 8) ? 8 : 0));
                uint32_t col = (uint32_t)(wn*32 + j2*16 + ((lane & 16) ? 8 : 0));
                ldsm4t(b2[j2], sV + row * 144 + col * 2);
            }
            #pragma unroll
            for (int i = 0; i < 2; i++)
                #pragma unroll
                for (int j = 0; j < 4; j++) {
                    int j2 = j >> 1, hh = (j & 1) * 2;
                    mma16816h(acc[i][j], a[i], b2[j2][hh], b2[j2][hh+1]);
                }
        }
        __syncthreads();
    }

    #pragma unroll
    for (int i = 0; i < 2; i++) {
        int qlo = m0 + wm*32 + i*16 + (lane >> 2);
        #pragma unroll
        for (int half = 0; half < 2; half++) {
            int q = qlo + half * 8;
            #pragma unroll
            for (int j = 0; j < 4; j++) {
                int hd = wn*32 + j*8 + 2*(lane & 3);
                float v0 = acc[i][j][half*2 + 0];
                float v1 = acc[i][j][half*2 + 1];
                size_t o = ((size_t)(b * 1024 + q)) * 1024 + h * 64 + hd;
                ushort_t h0,l0,h1,l1;
                split1h(v0, h0, l0); split1h(v1, h1, l1);
                *reinterpret_cast<ushort2*>(g_Xhi + o) = make_ushort2(h0, h1);
                *reinterpret_cast<ushort2*>(g_Xlo + o) = make_ushort2(l0, l1);
            }
        }
    }
}

// ---------------------------------------------------------------------------
extern "C" void kernel_launch(void* const* d_in, const int* in_sizes, int n_in,
                              void* d_out, int out_size)
{
    (void)in_sizes; (void)n_in; (void)out_size;
    const float* query = (const float*)d_in[0];
    const float* key   = (const float*)d_in[1];
    const float* value = (const float*)d_in[2];
    const float* Wq = (const float*)d_in[3];  const float* bq = (const float*)d_in[4];
    const float* Wk = (const float*)d_in[5];  const float* bk = (const float*)d_in[6];
    const float* Wv = (const float*)d_in[7];  const float* bv = (const float*)d_in[8];
    const float* Wo = (const float*)d_in[9];  const float* bo = (const float*)d_in[10];
    const float* Wc = (const float*)d_in[11]; const float* bc = (const float*)d_in[12];

    float* out = (float*)d_out;
    float* attn_out = out + (size_t)BB * SS * DD;

    static bool attr_done = false;
    if (!attr_done) {
        cudaFuncSetAttribute(proj_qkv,   cudaFuncAttributeMaxDynamicSharedMemorySize, PJ_SMEM);
        cudaFuncSetAttribute(proj_out,   cudaFuncAttributeMaxDynamicSharedMemorySize, PJ_SMEM);
        cudaFuncSetAttribute(scores_mma, cudaFuncAttributeMaxDynamicSharedMemorySize, SC_SMEM);
        cudaFuncSetAttribute(pv_mma,     cudaFuncAttributeMaxDynamicSharedMemorySize, PV_SMEM);
        attr_done = true;
    }

    const int NACT4 = NACT / 4;

    // all splits up front (merged launches)
    split_act3<<<dim3(NACT4/256, 3), 256>>>(
        (const float4*)query, (const float4*)key, (const float4*)value);
    split_wT4<<<dim3(32, 32, 4), 256>>>(Wq, Wk, Wv, Wo);

    // Q,K,V projections in one launch
    proj_qkv<<<dim3(8, 32, 3), 256, PJ_SMEM>>>(bq, bk, bv);

    scores_mma<<<dim3(8, 8, BB*HH), 256, SC_SMEM>>>();
    softmax_attnc<<<BB * SS, 256>>>(Wc, bc, attn_out);
    pv_mma<<<dim3(8, BB*HH), 256, PV_SMEM>>>();

    proj_out<<<dim3(8, 32), 256, PJ_SMEM>>>(bo, out);
}